// round 3
// baseline (speedup 1.0000x reference)
#include <cuda_runtime.h>
#include <cuda_bf16.h>
#include <cstdint>

// ---------------------------------------------------------------------------
// MambaBlock: B=4, L=512, d_model=128, d_inner=d_state=256
// rows = B*L = 2048
// Pipeline:
//   xproj = x @ W_in                      (2048 x 512, K=128)
//   delta = xs @ W_delta                  (2048 x 256, K=256)  xs = xproj[:, :256]
//   Bv    = xs @ W_B                      (2048 x 256)
//   Cv    = xs @ W_C                      (2048 x 256)
//   scan over l (state (b, d=256, n=256)):
//     s[b,d,n] = exp(delta[b,l,d]*A[d,n])*s + delta[b,l,d]*Bv[b,l,n]*xs[b,l,n]
//     y[b,l,d] = sum_n s[b,d,n]*Cv[b,l,n]
//     g[b,l,d] = y * silu(z[b,l,d])       z = xproj[:, 256:512]  (fused in scan)
//   out = g @ W_out                       (2048 x 128, K=256)
//
// All scratch lives in __device__ globals referenced directly from device
// code; kernel_launch performs kernel launches ONLY (graph-capture safe).
// ---------------------------------------------------------------------------

#define ROWS 2048
#define DI   256
#define DM   128

__device__ float g_xproj[ROWS * 512];
__device__ float g_delta[ROWS * DI];
__device__ float g_Bv[ROWS * DI];
__device__ float g_Cv[ROWS * DI];
__device__ float g_y[ROWS * DI];

__device__ __forceinline__ float ex2f(float x) {
    float r;
    asm("ex2.approx.ftz.f32 %0, %1;" : "=f"(r) : "f"(x));
    return r;
}

__device__ __forceinline__ void load8(float* r, const float* __restrict__ p) {
    float4 u = *(const float4*)p;
    float4 v = *(const float4*)(p + 4);
    r[0] = u.x; r[1] = u.y; r[2] = u.z; r[3] = u.w;
    r[4] = v.x; r[5] = v.y; r[6] = v.z; r[7] = v.w;
}

// ---------------------------------------------------------------------------
// fp32 tiled GEMM body: C[M,N] = A[M,K] @ B[K,N], row-major, explicit lds.
// 64x64 tile, BK=16, 256 threads, 4x4 accumulators per thread.
// Requires M%64==0, N%64==0, K%16==0, lda/ldb/ldc %4==0 (all true here).
// ---------------------------------------------------------------------------
__device__ __forceinline__ void gemm_body(
    const float* __restrict__ A, const float* __restrict__ B, float* __restrict__ C,
    int N_unused, int K, int lda, int ldb, int ldc)
{
    __shared__ float As[16][64];
    __shared__ float Bs[16][64];

    const int tx = threadIdx.x & 15;
    const int ty = threadIdx.x >> 4;
    const int rowBase = blockIdx.y * 64;
    const int colBase = blockIdx.x * 64;

    const int lr = threadIdx.x >> 2;          // 0..63  (A row within tile)
    const int lk = (threadIdx.x & 3) << 2;    // 0,4,8,12
    const int bk = threadIdx.x >> 4;          // 0..15  (B k within tile)
    const int bc = (threadIdx.x & 15) << 2;   // 0..60

    float acc[4][4] = {};

    for (int k0 = 0; k0 < K; k0 += 16) {
        float4 av = *(const float4*)(A + (size_t)(rowBase + lr) * lda + k0 + lk);
        As[lk + 0][lr] = av.x;
        As[lk + 1][lr] = av.y;
        As[lk + 2][lr] = av.z;
        As[lk + 3][lr] = av.w;
        *(float4*)&Bs[bk][bc] = *(const float4*)(B + (size_t)(k0 + bk) * ldb + colBase + bc);
        __syncthreads();

        #pragma unroll
        for (int k = 0; k < 16; k++) {
            float4 a4 = *(const float4*)&As[k][ty << 2];
            float4 b4 = *(const float4*)&Bs[k][tx << 2];
            acc[0][0] += a4.x * b4.x; acc[0][1] += a4.x * b4.y;
            acc[0][2] += a4.x * b4.z; acc[0][3] += a4.x * b4.w;
            acc[1][0] += a4.y * b4.x; acc[1][1] += a4.y * b4.y;
            acc[1][2] += a4.y * b4.z; acc[1][3] += a4.y * b4.w;
            acc[2][0] += a4.z * b4.x; acc[2][1] += a4.z * b4.y;
            acc[2][2] += a4.z * b4.z; acc[2][3] += a4.z * b4.w;
            acc[3][0] += a4.w * b4.x; acc[3][1] += a4.w * b4.y;
            acc[3][2] += a4.w * b4.z; acc[3][3] += a4.w * b4.w;
        }
        __syncthreads();
    }

    #pragma unroll
    for (int i = 0; i < 4; i++) {
        float4 v = make_float4(acc[i][0], acc[i][1], acc[i][2], acc[i][3]);
        *(float4*)(C + (size_t)(rowBase + (ty << 2) + i) * ldc + colBase + (tx << 2)) = v;
    }
}

// Wrappers naming device-global scratch directly (no host symbol lookups).
__global__ void __launch_bounds__(256) k_in_proj(const float* __restrict__ x,
                                                 const float* __restrict__ W_in) {
    gemm_body(x, W_in, g_xproj, 512, DM, DM, 512, 512);
}
__global__ void __launch_bounds__(256) k_delta(const float* __restrict__ W) {
    gemm_body(g_xproj, W, g_delta, DI, DI, 512, DI, DI);
}
__global__ void __launch_bounds__(256) k_B(const float* __restrict__ W) {
    gemm_body(g_xproj, W, g_Bv, DI, DI, 512, DI, DI);
}
__global__ void __launch_bounds__(256) k_C(const float* __restrict__ W) {
    gemm_body(g_xproj, W, g_Cv, DI, DI, 512, DI, DI);
}
__global__ void __launch_bounds__(256) k_out_proj(const float* __restrict__ W_out,
                                                  float* __restrict__ out) {
    gemm_body(g_y, W_out, out, DM, DI, DI, DM, DM);
}

// ---------------------------------------------------------------------------
// Sequential selective scan. Grid (32, 4): blockIdx.y = batch,
// blockIdx.x = tile of 8 d-channels. 8 warps/CTA, one warp per d channel;
// each lane owns 8 contiguous n-cells of state in registers.
// Software-pipelined: loads for step l+1 issued before computing step l.
// SiLU gating fused into the per-step store (lane 0).
// ---------------------------------------------------------------------------
__global__ void __launch_bounds__(256) scan_kernel(const float* __restrict__ A)
{
    const int b    = blockIdx.y;
    const int wid  = threadIdx.x >> 5;
    const int lane = threadIdx.x & 31;
    const int d    = blockIdx.x * 8 + wid;
    const int no   = lane << 3;                 // n offset: lane*8
    const float LOG2E = 1.4426950408889634f;

    float a[8];
    load8(a, A + d * 256 + no);
    #pragma unroll
    for (int j = 0; j < 8; j++) a[j] *= LOG2E;   // exp(x) = 2^(x*log2e)

    float s[8] = {0.f, 0.f, 0.f, 0.f, 0.f, 0.f, 0.f, 0.f};

    const int base = b * 512;

    // prefetch l = 0
    float dv = g_delta[base * 256 + d];
    float zv = g_xproj[base * 512 + 256 + d];
    float bv[8], cv[8], xv[8];
    load8(bv, g_Bv + base * 256 + no);
    load8(cv, g_Cv + base * 256 + no);
    load8(xv, g_xproj + base * 512 + no);

    for (int l = 0; l < 512; l++) {
        const int nrow = base + ((l < 511) ? (l + 1) : l);
        // issue next-step loads early (independent of state)
        float dv_n = g_delta[nrow * 256 + d];
        float zv_n = g_xproj[nrow * 512 + 256 + d];
        float bn[8], cn[8], xn[8];
        load8(bn, g_Bv + nrow * 256 + no);
        load8(cn, g_Cv + nrow * 256 + no);
        load8(xn, g_xproj + nrow * 512 + no);

        // state update + output dot
        float acc = 0.f;
        #pragma unroll
        for (int j = 0; j < 8; j++) {
            s[j] = ex2f(dv * a[j]) * s[j] + dv * (bv[j] * xv[j]);
            acc += s[j] * cv[j];
        }
        // warp reduce over n (32 lanes)
        acc += __shfl_xor_sync(0xffffffffu, acc, 16);
        acc += __shfl_xor_sync(0xffffffffu, acc, 8);
        acc += __shfl_xor_sync(0xffffffffu, acc, 4);
        acc += __shfl_xor_sync(0xffffffffu, acc, 2);
        acc += __shfl_xor_sync(0xffffffffu, acc, 1);
        if (lane == 0) {
            float sg = 1.f / (1.f + __expf(-zv));     // silu(z) = z*sigmoid(z)
            g_y[(base + l) * 256 + d] = acc * (zv * sg);
        }

        dv = dv_n; zv = zv_n;
        #pragma unroll
        for (int j = 0; j < 8; j++) { bv[j] = bn[j]; cv[j] = cn[j]; xv[j] = xn[j]; }
    }
}

extern "C" void kernel_launch(void* const* d_in, const int* in_sizes, int n_in,
                              void* d_out, int out_size)
{
    const float* x       = (const float*)d_in[0];
    const float* W_in    = (const float*)d_in[1];
    const float* W_delta = (const float*)d_in[2];
    const float* W_B     = (const float*)d_in[3];
    const float* W_C     = (const float*)d_in[4];
    const float* W_out   = (const float*)d_in[5];
    const float* A       = (const float*)d_in[6];
    float* out = (float*)d_out;

    // in_proj: (2048 x 128) @ (128 x 512)
    k_in_proj<<<dim3(8, 32), 256>>>(x, W_in);
    // delta / B / C projections: xs = xproj[:, :256] (lda = 512)
    k_delta<<<dim3(4, 32), 256>>>(W_delta);
    k_B    <<<dim3(4, 32), 256>>>(W_B);
    k_C    <<<dim3(4, 32), 256>>>(W_C);
    // selective scan + fused silu gate -> g_y
    scan_kernel<<<dim3(32, 4), 256>>>(A);
    // out_proj: (2048 x 256) @ (256 x 128)
    k_out_proj<<<dim3(2, 32), 256>>>(W_out, out);
}

// round 4
// speedup vs baseline: 1.2881x; 1.2881x over previous
#include <cuda_runtime.h>
#include <cuda_bf16.h>
#include <cstdint>

// ---------------------------------------------------------------------------
// MambaBlock: B=4, L=512, d_model=128, d_inner=d_state=256, rows = 2048
//   xproj = x @ W_in                       (2048 x 512, K=128)
//   delta = xs @ W_delta ; Bv = xs @ W_B ; Cv = xs @ W_C   (fused, z-indexed)
//       B-epilogue stores xb = Bv * xs  (elementwise, saves scan work)
//   scan: s[b,d,n] = exp(delta*A[d,n])*s + delta*xb[b,l,n]
//         y[b,l,d] = sum_n s*Cv ;  g = y * silu(z)   (fused)
//   out = g @ W_out                        (2048 x 128, K=256)
// kernel_launch performs kernel launches ONLY (graph-capture safe).
// ---------------------------------------------------------------------------

#define ROWS 2048
#define DI   256
#define DM   128

__device__ float g_xproj[ROWS * 512];
__device__ float g_delta[ROWS * DI];
__device__ float g_Bv[ROWS * DI];    // holds xb = Bv * xs after k_dbc
__device__ float g_Cv[ROWS * DI];
__device__ float g_y[ROWS * DI];

__device__ __forceinline__ float ex2f(float x) {
    float r;
    asm("ex2.approx.ftz.f32 %0, %1;" : "=f"(r) : "f"(x));
    return r;
}

__device__ __forceinline__ void load8(float* r, const float* __restrict__ p) {
    float4 u = *(const float4*)p;
    float4 v = *(const float4*)(p + 4);
    r[0] = u.x; r[1] = u.y; r[2] = u.z; r[3] = u.w;
    r[4] = v.x; r[5] = v.y; r[6] = v.z; r[7] = v.w;
}

// ---------------------------------------------------------------------------
// fp32 tiled GEMM body: 64x64 tile, BK=16, 256 threads, 4x4 per thread.
// mul_xs: multiply output elementwise by g_xproj[row, col] (xs) before store.
// ---------------------------------------------------------------------------
__device__ __forceinline__ void gemm_body(
    const float* __restrict__ A, const float* __restrict__ B, float* __restrict__ C,
    int K, int lda, int ldb, int ldc, bool mul_xs)
{
    __shared__ float As[16][64];
    __shared__ float Bs[16][64];

    const int tx = threadIdx.x & 15;
    const int ty = threadIdx.x >> 4;
    const int rowBase = blockIdx.y * 64;
    const int colBase = blockIdx.x * 64;

    const int lr = threadIdx.x >> 2;          // 0..63
    const int lk = (threadIdx.x & 3) << 2;    // 0,4,8,12
    const int bk = threadIdx.x >> 4;          // 0..15
    const int bc = (threadIdx.x & 15) << 2;   // 0..60

    float acc[4][4] = {};

    for (int k0 = 0; k0 < K; k0 += 16) {
        float4 av = *(const float4*)(A + (size_t)(rowBase + lr) * lda + k0 + lk);
        As[lk + 0][lr] = av.x;
        As[lk + 1][lr] = av.y;
        As[lk + 2][lr] = av.z;
        As[lk + 3][lr] = av.w;
        *(float4*)&Bs[bk][bc] = *(const float4*)(B + (size_t)(k0 + bk) * ldb + colBase + bc);
        __syncthreads();

        #pragma unroll
        for (int k = 0; k < 16; k++) {
            float4 a4 = *(const float4*)&As[k][ty << 2];
            float4 b4 = *(const float4*)&Bs[k][tx << 2];
            acc[0][0] += a4.x * b4.x; acc[0][1] += a4.x * b4.y;
            acc[0][2] += a4.x * b4.z; acc[0][3] += a4.x * b4.w;
            acc[1][0] += a4.y * b4.x; acc[1][1] += a4.y * b4.y;
            acc[1][2] += a4.y * b4.z; acc[1][3] += a4.y * b4.w;
            acc[2][0] += a4.z * b4.x; acc[2][1] += a4.z * b4.y;
            acc[2][2] += a4.z * b4.z; acc[2][3] += a4.z * b4.w;
            acc[3][0] += a4.w * b4.x; acc[3][1] += a4.w * b4.y;
            acc[3][2] += a4.w * b4.z; acc[3][3] += a4.w * b4.w;
        }
        __syncthreads();
    }

    #pragma unroll
    for (int i = 0; i < 4; i++) {
        const int row = rowBase + (ty << 2) + i;
        float4 v = make_float4(acc[i][0], acc[i][1], acc[i][2], acc[i][3]);
        if (mul_xs) {
            float4 xs4 = *(const float4*)(g_xproj + (size_t)row * 512 + colBase + (tx << 2));
            v.x *= xs4.x; v.y *= xs4.y; v.z *= xs4.z; v.w *= xs4.w;
        }
        *(float4*)(C + (size_t)row * ldc + colBase + (tx << 2)) = v;
    }
}

__global__ void __launch_bounds__(256) k_in_proj(const float* __restrict__ x,
                                                 const float* __restrict__ W_in) {
    gemm_body(x, W_in, g_xproj, DM, DM, 512, 512, false);
}

// Fused delta/B/C projections: blockIdx.z selects. 384 CTAs total.
__global__ void __launch_bounds__(256) k_dbc(const float* __restrict__ Wd,
                                             const float* __restrict__ Wb,
                                             const float* __restrict__ Wc) {
    const float* W = (blockIdx.z == 0) ? Wd : ((blockIdx.z == 1) ? Wb : Wc);
    float* C = (blockIdx.z == 0) ? g_delta : ((blockIdx.z == 1) ? g_Bv : g_Cv);
    gemm_body(g_xproj, W, C, DI, 512, DI, DI, blockIdx.z == 1);
}

// out_proj on 32x64 tiles -> 128 CTAs. 256 threads, 2x4 per thread.
__global__ void __launch_bounds__(256) k_out_proj(const float* __restrict__ W_out,
                                                  float* __restrict__ out) {
    __shared__ float As[16][32];
    __shared__ float Bs[16][64];

    const int tx = threadIdx.x & 15;
    const int ty = threadIdx.x >> 4;          // 0..15 -> rows ty*2, ty*2+1
    const int rowBase = blockIdx.y * 32;
    const int colBase = blockIdx.x * 64;

    const int lr = threadIdx.x >> 3;          // 0..31
    const int lk = (threadIdx.x & 7) << 1;    // 0,2,..,14
    const int bk = threadIdx.x >> 4;
    const int bc = (threadIdx.x & 15) << 2;

    float acc[2][4] = {};

    for (int k0 = 0; k0 < DI; k0 += 16) {
        float2 av = *(const float2*)(g_y + (size_t)(rowBase + lr) * DI + k0 + lk);
        As[lk + 0][lr] = av.x;
        As[lk + 1][lr] = av.y;
        *(float4*)&Bs[bk][bc] = *(const float4*)(W_out + (size_t)(k0 + bk) * DM + colBase + bc);
        __syncthreads();

        #pragma unroll
        for (int k = 0; k < 16; k++) {
            float a0 = As[k][(ty << 1) + 0];
            float a1 = As[k][(ty << 1) + 1];
            float4 b4 = *(const float4*)&Bs[k][tx << 2];
            acc[0][0] += a0 * b4.x; acc[0][1] += a0 * b4.y;
            acc[0][2] += a0 * b4.z; acc[0][3] += a0 * b4.w;
            acc[1][0] += a1 * b4.x; acc[1][1] += a1 * b4.y;
            acc[1][2] += a1 * b4.z; acc[1][3] += a1 * b4.w;
        }
        __syncthreads();
    }

    #pragma unroll
    for (int i = 0; i < 2; i++) {
        float4 v = make_float4(acc[i][0], acc[i][1], acc[i][2], acc[i][3]);
        *(float4*)(out + (size_t)(rowBase + (ty << 1) + i) * DM + colBase + (tx << 2)) = v;
    }
}

// ---------------------------------------------------------------------------
// Selective scan. Grid (32, 4): blockIdx.y = batch, blockIdx.x = 8-d tile.
// One warp per d channel; each lane owns 8 n-cells of state in registers.
// Depth-3 software pipeline via 4-slot rotating register file (#pragma
// unroll 4 makes all slot indices compile-time constants -> no spills).
// SiLU gating fused into the per-step store (lane 0).
// ---------------------------------------------------------------------------
__global__ void __launch_bounds__(256) scan_kernel(const float* __restrict__ A)
{
    const int b    = blockIdx.y;
    const int wid  = threadIdx.x >> 5;
    const int lane = threadIdx.x & 31;
    const int d    = blockIdx.x * 8 + wid;
    const int no   = lane << 3;
    const float LOG2E = 1.4426950408889634f;

    float a[8];
    load8(a, A + d * 256 + no);
    #pragma unroll
    for (int j = 0; j < 8; j++) a[j] *= LOG2E;   // exp(x) = 2^(x*log2e)

    float s[8] = {0.f, 0.f, 0.f, 0.f, 0.f, 0.f, 0.f, 0.f};

    const int base = b * 512;
    const float* __restrict__ xbp = g_Bv    + (size_t)base * 256 + no;
    const float* __restrict__ cvp = g_Cv    + (size_t)base * 256 + no;
    const float* __restrict__ dvp = g_delta + (size_t)base * 256 + d;
    const float* __restrict__ zvp = g_xproj + (size_t)base * 512 + 256 + d;

    float xb[4][8], cv[4][8], dvr[4], zvr[4];

    // prologue: fill slots 0..2 with steps 0..2
    #pragma unroll
    for (int p = 0; p < 3; p++) {
        load8(xb[p], xbp + (size_t)p * 256);
        load8(cv[p], cvp + (size_t)p * 256);
        dvr[p] = dvp[(size_t)p * 256];
        zvr[p] = zvp[(size_t)p * 512];
    }

    #pragma unroll 4
    for (int l = 0; l < 512; l++) {
        // prefetch step l+3 into the slot freed at l-1
        const int lp = (l + 3 < 512) ? (l + 3) : 511;
        const int sp = (l + 3) & 3;
        load8(xb[sp], xbp + (size_t)lp * 256);
        load8(cv[sp], cvp + (size_t)lp * 256);
        dvr[sp] = dvp[(size_t)lp * 256];
        zvr[sp] = zvp[(size_t)lp * 512];

        const int sc = l & 3;
        const float dv = dvr[sc];
        float acc = 0.f;
        #pragma unroll
        for (int j = 0; j < 8; j++) {
            float e = ex2f(dv * a[j]);
            s[j] = fmaf(e, s[j], dv * xb[sc][j]);
            acc = fmaf(s[j], cv[sc][j], acc);
        }
        acc += __shfl_xor_sync(0xffffffffu, acc, 16);
        acc += __shfl_xor_sync(0xffffffffu, acc, 8);
        acc += __shfl_xor_sync(0xffffffffu, acc, 4);
        acc += __shfl_xor_sync(0xffffffffu, acc, 2);
        acc += __shfl_xor_sync(0xffffffffu, acc, 1);
        if (lane == 0) {
            const float zv = zvr[sc];
            const float sg = 1.f / (1.f + __expf(-zv));   // silu(z) = z*sigmoid(z)
            g_y[(size_t)(base + l) * 256 + d] = acc * (zv * sg);
        }
    }
}

extern "C" void kernel_launch(void* const* d_in, const int* in_sizes, int n_in,
                              void* d_out, int out_size)
{
    const float* x       = (const float*)d_in[0];
    const float* W_in    = (const float*)d_in[1];
    const float* W_delta = (const float*)d_in[2];
    const float* W_B     = (const float*)d_in[3];
    const float* W_C     = (const float*)d_in[4];
    const float* W_out   = (const float*)d_in[5];
    const float* A       = (const float*)d_in[6];
    float* out = (float*)d_out;

    k_in_proj <<<dim3(8, 32),    256>>>(x, W_in);
    k_dbc     <<<dim3(4, 32, 3), 256>>>(W_delta, W_B, W_C);
    scan_kernel<<<dim3(32, 4),   256>>>(A);
    k_out_proj<<<dim3(2, 64),    256>>>(W_out, out);
}

// round 5
// speedup vs baseline: 1.3099x; 1.0169x over previous
#include <cuda_runtime.h>
#include <cuda_bf16.h>
#include <cstdint>

// ---------------------------------------------------------------------------
// MambaBlock: B=4, L=512, d_model=128, d_inner=d_state=256, rows = 2048
//   xproj = x @ W_in                       (2048 x 512, K=128)
//   delta = xs @ W_delta ; Bv = xs @ W_B ; Cv = xs @ W_C   (fused, z-indexed)
//       B-epilogue stores xb = Bv * xs  (elementwise, saves scan work)
//   scan: s[b,d,n] = exp(delta*A[d,n])*s + delta*xb[b,l,n]
//         y[b,l,d] = sum_n s*Cv ;  g = y * silu(z)   (fused)
//   out = g @ W_out                        (2048 x 128, K=256)
// kernel_launch performs kernel launches ONLY (graph-capture safe).
// ---------------------------------------------------------------------------

#define ROWS 2048
#define DI   256
#define DM   128

__device__ float g_xproj[ROWS * 512];
__device__ float g_delta[ROWS * DI];
__device__ float g_Bv[ROWS * DI];    // holds xb = Bv * xs after k_dbc
__device__ float g_Cv[ROWS * DI];
__device__ float g_y[ROWS * DI];

__device__ __forceinline__ float ex2f(float x) {
    float r;
    asm("ex2.approx.ftz.f32 %0, %1;" : "=f"(r) : "f"(x));
    return r;
}

__device__ __forceinline__ void load8(float* r, const float* __restrict__ p) {
    float4 u = *(const float4*)p;
    float4 v = *(const float4*)(p + 4);
    r[0] = u.x; r[1] = u.y; r[2] = u.z; r[3] = u.w;
    r[4] = v.x; r[5] = v.y; r[6] = v.z; r[7] = v.w;
}

// ---------------------------------------------------------------------------
// fp32 tiled GEMM body, double-buffered smem: 64x64 tile, BK=16, 256 thr,
// 4x4 accumulators. Global loads for tile k+1 are issued before the compute
// of tile k, so their latency overlaps the 16-step FMA block. One
// __syncthreads() per k-tile.
// mul_xs: multiply output elementwise by g_xproj[row, col] (xs) before store.
// ---------------------------------------------------------------------------
__device__ __forceinline__ void gemm_body(
    const float* __restrict__ A, const float* __restrict__ B, float* __restrict__ C,
    int K, int lda, int ldb, int ldc, bool mul_xs)
{
    __shared__ float As[2][16][64];
    __shared__ float Bs[2][16][64];

    const int tx = threadIdx.x & 15;
    const int ty = threadIdx.x >> 4;
    const int rowBase = blockIdx.y * 64;
    const int colBase = blockIdx.x * 64;

    const int lr = threadIdx.x >> 2;          // 0..63  (A row in tile)
    const int lk = (threadIdx.x & 3) << 2;    // 0,4,8,12
    const int bk = threadIdx.x >> 4;          // 0..15  (B k in tile)
    const int bc = (threadIdx.x & 15) << 2;   // 0..60

    const float* Aptr = A + (size_t)(rowBase + lr) * lda + lk;
    const float* Bptr = B + (size_t)bk * ldb + colBase + bc;

    float acc[4][4] = {};
    const int nT = K >> 4;

    // preload tile 0 into regs
    float4 av = *(const float4*)Aptr;
    float4 bv = *(const float4*)Bptr;

    for (int kt = 0; kt < nT; kt++) {
        const int p = kt & 1;
        // stage current tile regs -> smem buffer p
        As[p][lk + 0][lr] = av.x;
        As[p][lk + 1][lr] = av.y;
        As[p][lk + 2][lr] = av.z;
        As[p][lk + 3][lr] = av.w;
        *(float4*)&Bs[p][bk][bc] = bv;
        __syncthreads();

        // issue next tile's global loads (latency overlaps compute below)
        if (kt + 1 < nT) {
            av = *(const float4*)(Aptr + (kt + 1) * 16);
            bv = *(const float4*)(Bptr + (size_t)(kt + 1) * 16 * ldb);
        }

        #pragma unroll
        for (int k = 0; k < 16; k++) {
            float4 a4 = *(const float4*)&As[p][k][ty << 2];
            float4 b4 = *(const float4*)&Bs[p][k][tx << 2];
            acc[0][0] += a4.x * b4.x; acc[0][1] += a4.x * b4.y;
            acc[0][2] += a4.x * b4.z; acc[0][3] += a4.x * b4.w;
            acc[1][0] += a4.y * b4.x; acc[1][1] += a4.y * b4.y;
            acc[1][2] += a4.y * b4.z; acc[1][3] += a4.y * b4.w;
            acc[2][0] += a4.z * b4.x; acc[2][1] += a4.z * b4.y;
            acc[2][2] += a4.z * b4.z; acc[2][3] += a4.z * b4.w;
            acc[3][0] += a4.w * b4.x; acc[3][1] += a4.w * b4.y;
            acc[3][2] += a4.w * b4.z; acc[3][3] += a4.w * b4.w;
        }
        // no trailing sync: next iteration stores to the OTHER buffer, and
        // every thread already passed this iteration's sync.
        __syncthreads();
    }

    #pragma unroll
    for (int i = 0; i < 4; i++) {
        const int row = rowBase + (ty << 2) + i;
        float4 v = make_float4(acc[i][0], acc[i][1], acc[i][2], acc[i][3]);
        if (mul_xs) {
            float4 xs4 = *(const float4*)(g_xproj + (size_t)row * 512 + colBase + (tx << 2));
            v.x *= xs4.x; v.y *= xs4.y; v.z *= xs4.z; v.w *= xs4.w;
        }
        *(float4*)(C + (size_t)row * ldc + colBase + (tx << 2)) = v;
    }
}

__global__ void __launch_bounds__(256) k_in_proj(const float* __restrict__ x,
                                                 const float* __restrict__ W_in) {
    gemm_body(x, W_in, g_xproj, DM, DM, 512, 512, false);
}

// Fused delta/B/C projections: blockIdx.z selects. 384 CTAs total.
__global__ void __launch_bounds__(256) k_dbc(const float* __restrict__ Wd,
                                             const float* __restrict__ Wb,
                                             const float* __restrict__ Wc) {
    const float* W = (blockIdx.z == 0) ? Wd : ((blockIdx.z == 1) ? Wb : Wc);
    float* C = (blockIdx.z == 0) ? g_delta : ((blockIdx.z == 1) ? g_Bv : g_Cv);
    gemm_body(g_xproj, W, C, DI, 512, DI, DI, blockIdx.z == 1);
}

// out_proj: 32x64 tiles -> 128 CTAs, double-buffered, 2x4 per thread.
__global__ void __launch_bounds__(256) k_out_proj(const float* __restrict__ W_out,
                                                  float* __restrict__ out) {
    __shared__ float As[2][16][32];
    __shared__ float Bs[2][16][64];

    const int tx = threadIdx.x & 15;
    const int ty = threadIdx.x >> 4;
    const int rowBase = blockIdx.y * 32;
    const int colBase = blockIdx.x * 64;

    const int lr = threadIdx.x >> 3;          // 0..31
    const int lk = (threadIdx.x & 7) << 1;    // 0,2,..,14
    const int bk = threadIdx.x >> 4;
    const int bc = (threadIdx.x & 15) << 2;

    const float* Aptr = g_y + (size_t)(rowBase + lr) * DI + lk;
    const float* Bptr = W_out + (size_t)bk * DM + colBase + bc;

    float acc[2][4] = {};
    const int nT = DI >> 4;

    float2 av = *(const float2*)Aptr;
    float4 bv = *(const float4*)Bptr;

    for (int kt = 0; kt < nT; kt++) {
        const int p = kt & 1;
        As[p][lk + 0][lr] = av.x;
        As[p][lk + 1][lr] = av.y;
        *(float4*)&Bs[p][bk][bc] = bv;
        __syncthreads();

        if (kt + 1 < nT) {
            av = *(const float2*)(Aptr + (kt + 1) * 16);
            bv = *(const float4*)(Bptr + (size_t)(kt + 1) * 16 * DM);
        }

        #pragma unroll
        for (int k = 0; k < 16; k++) {
            float a0 = As[p][k][(ty << 1) + 0];
            float a1 = As[p][k][(ty << 1) + 1];
            float4 b4 = *(const float4*)&Bs[p][k][tx << 2];
            acc[0][0] += a0 * b4.x; acc[0][1] += a0 * b4.y;
            acc[0][2] += a0 * b4.z; acc[0][3] += a0 * b4.w;
            acc[1][0] += a1 * b4.x; acc[1][1] += a1 * b4.y;
            acc[1][2] += a1 * b4.z; acc[1][3] += a1 * b4.w;
        }
        __syncthreads();
    }

    #pragma unroll
    for (int i = 0; i < 2; i++) {
        float4 v = make_float4(acc[i][0], acc[i][1], acc[i][2], acc[i][3]);
        *(float4*)(out + (size_t)(rowBase + (ty << 1) + i) * DM + colBase + (tx << 2)) = v;
    }
}

// ---------------------------------------------------------------------------
// Selective scan. Grid (32, 4): blockIdx.y = batch, blockIdx.x = 8-d tile.
// One warp per d channel; each lane owns 8 n-cells of state in registers.
// Depth-7 software pipeline via 8-slot rotating register file (#pragma
// unroll 8 makes all slot indices compile-time constants). Loads issue
// ~600+ cycles ahead of use -> covers L2/DRAM latency.
// SiLU gating fused into the per-step store (lane 0).
// ---------------------------------------------------------------------------
__global__ void __launch_bounds__(256) scan_kernel(const float* __restrict__ A)
{
    const int b    = blockIdx.y;
    const int wid  = threadIdx.x >> 5;
    const int lane = threadIdx.x & 31;
    const int d    = blockIdx.x * 8 + wid;
    const int no   = lane << 3;
    const float LOG2E = 1.4426950408889634f;

    float a[8];
    load8(a, A + d * 256 + no);
    #pragma unroll
    for (int j = 0; j < 8; j++) a[j] *= LOG2E;   // exp(x) = 2^(x*log2e)

    float s[8] = {0.f, 0.f, 0.f, 0.f, 0.f, 0.f, 0.f, 0.f};

    const int base = b * 512;
    const float* __restrict__ xbp = g_Bv    + (size_t)base * 256 + no;
    const float* __restrict__ cvp = g_Cv    + (size_t)base * 256 + no;
    const float* __restrict__ dvp = g_delta + (size_t)base * 256 + d;
    const float* __restrict__ zvp = g_xproj + (size_t)base * 512 + 256 + d;

    float xb[8][8], cv[8][8], dvr[8], zvr[8];

    // prologue: fill slots 0..6 with steps 0..6
    #pragma unroll
    for (int p = 0; p < 7; p++) {
        load8(xb[p], xbp + (size_t)p * 256);
        load8(cv[p], cvp + (size_t)p * 256);
        dvr[p] = dvp[(size_t)p * 256];
        zvr[p] = zvp[(size_t)p * 512];
    }

    #pragma unroll 8
    for (int l = 0; l < 512; l++) {
        // prefetch step l+7 into the slot freed at l-1
        const int lp = (l + 7 < 512) ? (l + 7) : 511;
        const int sp = (l + 7) & 7;
        load8(xb[sp], xbp + (size_t)lp * 256);
        load8(cv[sp], cvp + (size_t)lp * 256);
        dvr[sp] = dvp[(size_t)lp * 256];
        zvr[sp] = zvp[(size_t)lp * 512];

        const int sc = l & 7;
        const float dv = dvr[sc];
        float acc = 0.f;
        #pragma unroll
        for (int j = 0; j < 8; j++) {
            float e = ex2f(dv * a[j]);
            s[j] = fmaf(e, s[j], dv * xb[sc][j]);
            acc = fmaf(s[j], cv[sc][j], acc);
        }
        acc += __shfl_xor_sync(0xffffffffu, acc, 16);
        acc += __shfl_xor_sync(0xffffffffu, acc, 8);
        acc += __shfl_xor_sync(0xffffffffu, acc, 4);
        acc += __shfl_xor_sync(0xffffffffu, acc, 2);
        acc += __shfl_xor_sync(0xffffffffu, acc, 1);
        if (lane == 0) {
            const float zv = zvr[sc];
            const float sg = 1.f / (1.f + __expf(-zv));   // silu(z) = z*sigmoid(z)
            g_y[(size_t)(base + l) * 256 + d] = acc * (zv * sg);
        }
    }
}

extern "C" void kernel_launch(void* const* d_in, const int* in_sizes, int n_in,
                              void* d_out, int out_size)
{
    const float* x       = (const float*)d_in[0];
    const float* W_in    = (const float*)d_in[1];
    const float* W_delta = (const float*)d_in[2];
    const float* W_B     = (const float*)d_in[3];
    const float* W_C     = (const float*)d_in[4];
    const float* W_out   = (const float*)d_in[5];
    const float* A       = (const float*)d_in[6];
    float* out = (float*)d_out;

    k_in_proj <<<dim3(8, 32),    256>>>(x, W_in);
    k_dbc     <<<dim3(4, 32, 3), 256>>>(W_delta, W_B, W_C);
    scan_kernel<<<dim3(32, 4),   256>>>(A);
    k_out_proj<<<dim3(2, 64),    256>>>(W_out, out);
}

// round 6
// speedup vs baseline: 1.3765x; 1.0509x over previous
#include <cuda_runtime.h>
#include <cuda_bf16.h>
#include <cstdint>

// ---------------------------------------------------------------------------
// MambaBlock: B=4, L=512, d_model=128, d_inner=d_state=256, rows = 2048
//   xproj = x @ W_in                       (2048 x 512, K=128)
//   delta = xs @ W_delta ; Bv = xs @ W_B ; Cv = xs @ W_C   (fused, z-indexed)
//       B-epilogue stores xb = Bv * xs
//   scan (CHUNKED, NC=8 chunks of T=64 for 8x parallelism):
//     pass A: per-chunk local scan from zero state -> raw y_local, S_end, sum(delta)
//     pass B: sequential combine of 8 chunk states (chunk decay = exp(a*sum_delta))
//     pass C: y += C_l . (s_in * prod exp(a*delta)); apply silu(z) gate
//   out = g @ W_out                        (2048 x 128, K=256)
// kernel_launch performs kernel launches ONLY (graph-capture safe).
// ---------------------------------------------------------------------------

#define ROWS 2048
#define DI   256
#define DM   128
#define NC   8      // chunks per batch
#define CT   64     // chunk length

__device__ float g_xproj[ROWS * 512];
__device__ float g_delta[ROWS * DI];
__device__ float g_Bv[ROWS * DI];     // xb = Bv * xs after k_dbc
__device__ float g_Cv[ROWS * DI];
__device__ float g_y[ROWS * DI];
__device__ float g_state[NC * 4 * DI * DI];   // [c][b][d][n]
__device__ float g_dsum[NC * 4 * DI];         // [c][b][d]

__device__ __forceinline__ float ex2f(float x) {
    float r;
    asm("ex2.approx.ftz.f32 %0, %1;" : "=f"(r) : "f"(x));
    return r;
}

__device__ __forceinline__ void load8(float* r, const float* __restrict__ p) {
    float4 u = *(const float4*)p;
    float4 v = *(const float4*)(p + 4);
    r[0] = u.x; r[1] = u.y; r[2] = u.z; r[3] = u.w;
    r[4] = v.x; r[5] = v.y; r[6] = v.z; r[7] = v.w;
}
__device__ __forceinline__ void store8(float* __restrict__ p, const float* r) {
    *(float4*)p       = make_float4(r[0], r[1], r[2], r[3]);
    *(float4*)(p + 4) = make_float4(r[4], r[5], r[6], r[7]);
}

// ---------------------------------------------------------------------------
// fp32 tiled GEMM body, double-buffered smem: 64x64 tile, BK=16, 256 thr.
// ---------------------------------------------------------------------------
__device__ __forceinline__ void gemm_body(
    const float* __restrict__ A, const float* __restrict__ B, float* __restrict__ C,
    int K, int lda, int ldb, int ldc, bool mul_xs)
{
    __shared__ float As[2][16][64];
    __shared__ float Bs[2][16][64];

    const int tx = threadIdx.x & 15;
    const int ty = threadIdx.x >> 4;
    const int rowBase = blockIdx.y * 64;
    const int colBase = blockIdx.x * 64;

    const int lr = threadIdx.x >> 2;
    const int lk = (threadIdx.x & 3) << 2;
    const int bk = threadIdx.x >> 4;
    const int bc = (threadIdx.x & 15) << 2;

    const float* Aptr = A + (size_t)(rowBase + lr) * lda + lk;
    const float* Bptr = B + (size_t)bk * ldb + colBase + bc;

    float acc[4][4] = {};
    const int nT = K >> 4;

    float4 av = *(const float4*)Aptr;
    float4 bv = *(const float4*)Bptr;

    for (int kt = 0; kt < nT; kt++) {
        const int p = kt & 1;
        As[p][lk + 0][lr] = av.x;
        As[p][lk + 1][lr] = av.y;
        As[p][lk + 2][lr] = av.z;
        As[p][lk + 3][lr] = av.w;
        *(float4*)&Bs[p][bk][bc] = bv;
        __syncthreads();

        if (kt + 1 < nT) {
            av = *(const float4*)(Aptr + (kt + 1) * 16);
            bv = *(const float4*)(Bptr + (size_t)(kt + 1) * 16 * ldb);
        }

        #pragma unroll
        for (int k = 0; k < 16; k++) {
            float4 a4 = *(const float4*)&As[p][k][ty << 2];
            float4 b4 = *(const float4*)&Bs[p][k][tx << 2];
            acc[0][0] += a4.x * b4.x; acc[0][1] += a4.x * b4.y;
            acc[0][2] += a4.x * b4.z; acc[0][3] += a4.x * b4.w;
            acc[1][0] += a4.y * b4.x; acc[1][1] += a4.y * b4.y;
            acc[1][2] += a4.y * b4.z; acc[1][3] += a4.y * b4.w;
            acc[2][0] += a4.z * b4.x; acc[2][1] += a4.z * b4.y;
            acc[2][2] += a4.z * b4.z; acc[2][3] += a4.z * b4.w;
            acc[3][0] += a4.w * b4.x; acc[3][1] += a4.w * b4.y;
            acc[3][2] += a4.w * b4.z; acc[3][3] += a4.w * b4.w;
        }
        __syncthreads();
    }

    #pragma unroll
    for (int i = 0; i < 4; i++) {
        const int row = rowBase + (ty << 2) + i;
        float4 v = make_float4(acc[i][0], acc[i][1], acc[i][2], acc[i][3]);
        if (mul_xs) {
            float4 xs4 = *(const float4*)(g_xproj + (size_t)row * 512 + colBase + (tx << 2));
            v.x *= xs4.x; v.y *= xs4.y; v.z *= xs4.z; v.w *= xs4.w;
        }
        *(float4*)(C + (size_t)row * ldc + colBase + (tx << 2)) = v;
    }
}

__global__ void __launch_bounds__(256) k_in_proj(const float* __restrict__ x,
                                                 const float* __restrict__ W_in) {
    gemm_body(x, W_in, g_xproj, DM, DM, 512, 512, false);
}

__global__ void __launch_bounds__(256) k_dbc(const float* __restrict__ Wd,
                                             const float* __restrict__ Wb,
                                             const float* __restrict__ Wc) {
    const float* W = (blockIdx.z == 0) ? Wd : ((blockIdx.z == 1) ? Wb : Wc);
    float* C = (blockIdx.z == 0) ? g_delta : ((blockIdx.z == 1) ? g_Bv : g_Cv);
    gemm_body(g_xproj, W, C, DI, 512, DI, DI, blockIdx.z == 1);
}

__global__ void __launch_bounds__(256) k_out_proj(const float* __restrict__ W_out,
                                                  float* __restrict__ out) {
    __shared__ float As[2][16][32];
    __shared__ float Bs[2][16][64];

    const int tx = threadIdx.x & 15;
    const int ty = threadIdx.x >> 4;
    const int rowBase = blockIdx.y * 32;
    const int colBase = blockIdx.x * 64;

    const int lr = threadIdx.x >> 3;
    const int lk = (threadIdx.x & 7) << 1;
    const int bk = threadIdx.x >> 4;
    const int bc = (threadIdx.x & 15) << 2;

    const float* Aptr = g_y + (size_t)(rowBase + lr) * DI + lk;
    const float* Bptr = W_out + (size_t)bk * DM + colBase + bc;

    float acc[2][4] = {};
    const int nT = DI >> 4;

    float2 av = *(const float2*)Aptr;
    float4 bv = *(const float4*)Bptr;

    for (int kt = 0; kt < nT; kt++) {
        const int p = kt & 1;
        As[p][lk + 0][lr] = av.x;
        As[p][lk + 1][lr] = av.y;
        *(float4*)&Bs[p][bk][bc] = bv;
        __syncthreads();

        if (kt + 1 < nT) {
            av = *(const float2*)(Aptr + (kt + 1) * 16);
            bv = *(const float4*)(Bptr + (size_t)(kt + 1) * 16 * DM);
        }

        #pragma unroll
        for (int k = 0; k < 16; k++) {
            float a0 = As[p][k][(ty << 1) + 0];
            float a1 = As[p][k][(ty << 1) + 1];
            float4 b4 = *(const float4*)&Bs[p][k][tx << 2];
            acc[0][0] += a0 * b4.x; acc[0][1] += a0 * b4.y;
            acc[0][2] += a0 * b4.z; acc[0][3] += a0 * b4.w;
            acc[1][0] += a1 * b4.x; acc[1][1] += a1 * b4.y;
            acc[1][2] += a1 * b4.z; acc[1][3] += a1 * b4.w;
        }
        __syncthreads();
    }

    #pragma unroll
    for (int i = 0; i < 2; i++) {
        float4 v = make_float4(acc[i][0], acc[i][1], acc[i][2], acc[i][3]);
        *(float4*)(out + (size_t)(rowBase + (ty << 1) + i) * DM + colBase + (tx << 2)) = v;
    }
}

// warp-level sum over 32 lanes
__device__ __forceinline__ float warp_sum(float v) {
    v += __shfl_xor_sync(0xffffffffu, v, 16);
    v += __shfl_xor_sync(0xffffffffu, v, 8);
    v += __shfl_xor_sync(0xffffffffu, v, 4);
    v += __shfl_xor_sync(0xffffffffu, v, 2);
    v += __shfl_xor_sync(0xffffffffu, v, 1);
    return v;
}

// ---------------------------------------------------------------------------
// Pass A: chunk-local scan from zero state. Grid (32 dtiles, NC, 4 batches)
// = 1024 CTAs, 8 warps each (warp per d, lane owns 8 n-cells).
// Writes RAW y_local (no gate), chunk-end state, and sum(delta) per (c,b,d).
// ---------------------------------------------------------------------------
__global__ void __launch_bounds__(256) scan_passA(const float* __restrict__ A)
{
    const int c    = blockIdx.y;
    const int b    = blockIdx.z;
    const int wid  = threadIdx.x >> 5;
    const int lane = threadIdx.x & 31;
    const int d    = blockIdx.x * 8 + wid;
    const int no   = lane << 3;
    const float LOG2E = 1.4426950408889634f;

    float a[8];
    load8(a, A + d * 256 + no);
    #pragma unroll
    for (int j = 0; j < 8; j++) a[j] *= LOG2E;

    float s[8] = {};
    float dsum = 0.f;

    const int row0 = b * 512 + c * CT;
    const float* __restrict__ xbp = g_Bv    + (size_t)row0 * 256 + no;
    const float* __restrict__ cvp = g_Cv    + (size_t)row0 * 256 + no;
    const float* __restrict__ dvp = g_delta + (size_t)row0 * 256 + d;

    float xb[2][8], cv[2][8], dvr[2];
    load8(xb[0], xbp); load8(cv[0], cvp); dvr[0] = dvp[0];

    #pragma unroll 2
    for (int t = 0; t < CT; t++) {
        const int tp = (t + 1 < CT) ? (t + 1) : t;
        const int sp = (t + 1) & 1;
        load8(xb[sp], xbp + (size_t)tp * 256);
        load8(cv[sp], cvp + (size_t)tp * 256);
        dvr[sp] = dvp[(size_t)tp * 256];

        const int sc = t & 1;
        const float dv = dvr[sc];
        dsum += dv;
        float acc = 0.f;
        #pragma unroll
        for (int j = 0; j < 8; j++) {
            float e = ex2f(dv * a[j]);
            s[j] = fmaf(e, s[j], dv * xb[sc][j]);
            acc = fmaf(s[j], cv[sc][j], acc);
        }
        acc = warp_sum(acc);
        if (lane == 0) g_y[(size_t)(row0 + t) * 256 + d] = acc;   // RAW
    }

    store8(g_state + ((size_t)(c * 4 + b) * 256 + d) * 256 + no, s);
    if (lane == 0) g_dsum[(c * 4 + b) * 256 + d] = dsum;
}

// ---------------------------------------------------------------------------
// Pass B: sequential combine across the NC chunks. Grid (32, 4), 8 warps.
// Rewrites g_state[c] from "chunk-end local state" to "incoming state s_in".
// ---------------------------------------------------------------------------
__global__ void __launch_bounds__(256) scan_passB(const float* __restrict__ A)
{
    const int b    = blockIdx.y;
    const int wid  = threadIdx.x >> 5;
    const int lane = threadIdx.x & 31;
    const int d    = blockIdx.x * 8 + wid;
    const int no   = lane << 3;
    const float LOG2E = 1.4426950408889634f;

    float a[8];
    load8(a, A + d * 256 + no);
    #pragma unroll
    for (int j = 0; j < 8; j++) a[j] *= LOG2E;

    float sin[8] = {};

    for (int c = 0; c < NC; c++) {
        float* slot = g_state + ((size_t)(c * 4 + b) * 256 + d) * 256 + no;
        float endv[8];
        load8(endv, slot);
        const float dsv = g_dsum[(c * 4 + b) * 256 + d];
        store8(slot, sin);                       // slot c := incoming state
        #pragma unroll
        for (int j = 0; j < 8; j++)
            sin[j] = fmaf(ex2f(dsv * a[j]), sin[j], endv[j]);
    }
}

// ---------------------------------------------------------------------------
// Pass C: correction + SiLU gate. Grid (32, NC, 4) = 1024 CTAs.
// w starts at s_in; per step w *= exp(a*delta); y += C . w; gate and store.
// ---------------------------------------------------------------------------
__global__ void __launch_bounds__(256) scan_passC(const float* __restrict__ A)
{
    const int c    = blockIdx.y;
    const int b    = blockIdx.z;
    const int wid  = threadIdx.x >> 5;
    const int lane = threadIdx.x & 31;
    const int d    = blockIdx.x * 8 + wid;
    const int no   = lane << 3;
    const float LOG2E = 1.4426950408889634f;

    float a[8];
    load8(a, A + d * 256 + no);
    #pragma unroll
    for (int j = 0; j < 8; j++) a[j] *= LOG2E;

    float w[8];
    load8(w, g_state + ((size_t)(c * 4 + b) * 256 + d) * 256 + no);

    const int row0 = b * 512 + c * CT;
    const float* __restrict__ cvp = g_Cv    + (size_t)row0 * 256 + no;
    const float* __restrict__ dvp = g_delta + (size_t)row0 * 256 + d;
    const float* __restrict__ zvp = g_xproj + (size_t)row0 * 512 + 256 + d;
    float*       __restrict__ yp  = g_y     + (size_t)row0 * 256 + d;

    float cv[2][8], dvr[2], zvr[2], yvr[2];
    load8(cv[0], cvp); dvr[0] = dvp[0]; zvr[0] = zvp[0]; yvr[0] = yp[0];

    #pragma unroll 2
    for (int t = 0; t < CT; t++) {
        const int tp = (t + 1 < CT) ? (t + 1) : t;
        const int sp = (t + 1) & 1;
        load8(cv[sp], cvp + (size_t)tp * 256);
        dvr[sp] = dvp[(size_t)tp * 256];
        zvr[sp] = zvp[(size_t)tp * 512];
        yvr[sp] = yp[(size_t)tp * 256];

        const int sc = t & 1;
        const float dv = dvr[sc];
        float acc = 0.f;
        #pragma unroll
        for (int j = 0; j < 8; j++) {
            w[j] *= ex2f(dv * a[j]);
            acc = fmaf(w[j], cv[sc][j], acc);
        }
        acc = warp_sum(acc);
        if (lane == 0) {
            const float zv = zvr[sc];
            const float sg = 1.f / (1.f + __expf(-zv));
            yp[(size_t)t * 256] = (yvr[sc] + acc) * (zv * sg);
        }
    }
}

extern "C" void kernel_launch(void* const* d_in, const int* in_sizes, int n_in,
                              void* d_out, int out_size)
{
    const float* x       = (const float*)d_in[0];
    const float* W_in    = (const float*)d_in[1];
    const float* W_delta = (const float*)d_in[2];
    const float* W_B     = (const float*)d_in[3];
    const float* W_C     = (const float*)d_in[4];
    const float* W_out   = (const float*)d_in[5];
    const float* A       = (const float*)d_in[6];
    float* out = (float*)d_out;

    k_in_proj <<<dim3(8, 32),     256>>>(x, W_in);
    k_dbc     <<<dim3(4, 32, 3),  256>>>(W_delta, W_B, W_C);
    scan_passA<<<dim3(32, NC, 4), 256>>>(A);
    scan_passB<<<dim3(32, 4),     256>>>(A);
    scan_passC<<<dim3(32, NC, 4), 256>>>(A);
    k_out_proj<<<dim3(2, 64),     256>>>(W_out, out);
}

// round 7
// speedup vs baseline: 1.4122x; 1.0259x over previous
#include <cuda_runtime.h>
#include <cuda_bf16.h>
#include <cstdint>

// ---------------------------------------------------------------------------
// MambaBlock: B=4, L=512, d_model=128, d_inner=d_state=256, rows = 2048
//   xproj = x @ W_in ; delta/Bv/Cv = xs @ {Wd,Wb,Wc} (fused, xb=Bv*xs epilogue)
//   chunked scan (NC=8 x CT=64): passA local scan, passB parallel combine,
//   passC correction + silu gate ; out = g @ W_out
// kernel_launch performs kernel launches ONLY (graph-capture safe).
// ---------------------------------------------------------------------------

#define ROWS 2048
#define DI   256
#define DM   128
#define NC   8
#define CT   64

__device__ float g_xproj[ROWS * 512];
__device__ float g_delta[ROWS * DI];
__device__ float g_Bv[ROWS * DI];     // xb = Bv * xs after k_dbc
__device__ float g_Cv[ROWS * DI];
__device__ float g_y[ROWS * DI];
__device__ float g_state[NC * 4 * DI * DI];   // [c][b][d][n]
__device__ float g_dsum[NC * 4 * DI];         // [c][b][d]

__device__ __forceinline__ float ex2f(float x) {
    float r;
    asm("ex2.approx.ftz.f32 %0, %1;" : "=f"(r) : "f"(x));
    return r;
}

__device__ __forceinline__ void load8(float* r, const float* __restrict__ p) {
    float4 u = *(const float4*)p;
    float4 v = *(const float4*)(p + 4);
    r[0] = u.x; r[1] = u.y; r[2] = u.z; r[3] = u.w;
    r[4] = v.x; r[5] = v.y; r[6] = v.z; r[7] = v.w;
}
__device__ __forceinline__ void store8(float* __restrict__ p, const float* r) {
    *(float4*)p       = make_float4(r[0], r[1], r[2], r[3]);
    *(float4*)(p + 4) = make_float4(r[4], r[5], r[6], r[7]);
}

// ---------------------------------------------------------------------------
// fp32 GEMM, 128 threads/CTA, double-buffered smem, TM x 64 tile, BK=16.
// Each thread: (TM/8) x 4 accumulators -> 16/32 FMA per k-step vs 3 LDS.128.
// ---------------------------------------------------------------------------
template<int TM, bool MUL_XS>
__device__ __forceinline__ void gemm_t(
    const float* __restrict__ A, const float* __restrict__ B, float* __restrict__ C,
    int K, int lda, int ldb, int ldc)
{
    constexpr int RPT = TM / 8;   // rows per thread (8 or 4)
    __shared__ float As[2][16][TM];
    __shared__ float Bs[2][16][64];

    const int tid = threadIdx.x;
    const int tx = tid & 15;            // col group (4 cols)
    const int ty = tid >> 4;            // row group (RPT rows), 0..7
    const int rowBase = blockIdx.y * TM;
    const int colBase = blockIdx.x * 64;

    // A-tile loader: TM*16 floats / 128 threads
    const int ar = (TM == 64) ? (tid & 63) : (tid & 31);
    const int ak = (TM == 64) ? ((tid >> 6) << 3) : ((tid >> 5) << 2);
    // B-tile loader: 16x64 floats / 128 threads (8 floats each)
    const int bk = tid >> 3;            // 0..15
    const int bc = (tid & 7) << 3;      // 0,8,..,56

    const float* Aptr = A + (size_t)(rowBase + ar) * lda + ak;
    const float* Bptr = B + (size_t)bk * ldb + colBase + bc;

    float acc[RPT][4] = {};
    const int nT = K >> 4;

    float4 a0 = *(const float4*)Aptr;
    float4 a1 = (TM == 64) ? *(const float4*)(Aptr + 4) : make_float4(0, 0, 0, 0);
    float4 b0 = *(const float4*)Bptr;
    float4 b1 = *(const float4*)(Bptr + 4);

    for (int kt = 0; kt < nT; kt++) {
        const int p = kt & 1;
        As[p][ak + 0][ar] = a0.x;
        As[p][ak + 1][ar] = a0.y;
        As[p][ak + 2][ar] = a0.z;
        As[p][ak + 3][ar] = a0.w;
        if (TM == 64) {
            As[p][ak + 4][ar] = a1.x;
            As[p][ak + 5][ar] = a1.y;
            As[p][ak + 6][ar] = a1.z;
            As[p][ak + 7][ar] = a1.w;
        }
        *(float4*)&Bs[p][bk][bc]     = b0;
        *(float4*)&Bs[p][bk][bc + 4] = b1;
        __syncthreads();

        if (kt + 1 < nT) {
            const float* An = Aptr + (kt + 1) * 16;
            const float* Bn = Bptr + (size_t)(kt + 1) * 16 * ldb;
            a0 = *(const float4*)An;
            if (TM == 64) a1 = *(const float4*)(An + 4);
            b0 = *(const float4*)Bn;
            b1 = *(const float4*)(Bn + 4);
        }

        #pragma unroll
        for (int k = 0; k < 16; k++) {
            float4 bq = *(const float4*)&Bs[p][k][tx << 2];
            #pragma unroll
            for (int r4 = 0; r4 < RPT; r4 += 4) {
                float4 aq = *(const float4*)&As[p][k][ty * RPT + r4];
                acc[r4 + 0][0] += aq.x * bq.x; acc[r4 + 0][1] += aq.x * bq.y;
                acc[r4 + 0][2] += aq.x * bq.z; acc[r4 + 0][3] += aq.x * bq.w;
                acc[r4 + 1][0] += aq.y * bq.x; acc[r4 + 1][1] += aq.y * bq.y;
                acc[r4 + 1][2] += aq.y * bq.z; acc[r4 + 1][3] += aq.y * bq.w;
                acc[r4 + 2][0] += aq.z * bq.x; acc[r4 + 2][1] += aq.z * bq.y;
                acc[r4 + 2][2] += aq.z * bq.z; acc[r4 + 2][3] += aq.z * bq.w;
                acc[r4 + 3][0] += aq.w * bq.x; acc[r4 + 3][1] += aq.w * bq.y;
                acc[r4 + 3][2] += aq.w * bq.z; acc[r4 + 3][3] += aq.w * bq.w;
            }
        }
        __syncthreads();
    }

    #pragma unroll
    for (int r = 0; r < RPT; r++) {
        const int row = rowBase + ty * RPT + r;
        float4 v = make_float4(acc[r][0], acc[r][1], acc[r][2], acc[r][3]);
        if (MUL_XS) {
            float4 xs4 = *(const float4*)(g_xproj + (size_t)row * 512 + colBase + (tx << 2));
            v.x *= xs4.x; v.y *= xs4.y; v.z *= xs4.z; v.w *= xs4.w;
        }
        *(float4*)(C + (size_t)row * ldc + colBase + (tx << 2)) = v;
    }
}

__global__ void __launch_bounds__(128) k_in_proj(const float* __restrict__ x,
                                                 const float* __restrict__ W_in) {
    gemm_t<64, false>(x, W_in, g_xproj, DM, DM, 512, 512);
}

__global__ void __launch_bounds__(128) k_dbc(const float* __restrict__ Wd,
                                             const float* __restrict__ Wb,
                                             const float* __restrict__ Wc) {
    if (blockIdx.z == 0)      gemm_t<64, false>(g_xproj, Wd, g_delta, DI, 512, DI, DI);
    else if (blockIdx.z == 1) gemm_t<64, true >(g_xproj, Wb, g_Bv,    DI, 512, DI, DI);
    else                      gemm_t<64, false>(g_xproj, Wc, g_Cv,    DI, 512, DI, DI);
}

__global__ void __launch_bounds__(128) k_out_proj(const float* __restrict__ W_out,
                                                  float* __restrict__ out) {
    gemm_t<32, false>(g_y, W_out, out, DI, DI, DM, DM);
}

__device__ __forceinline__ float warp_sum(float v) {
    v += __shfl_xor_sync(0xffffffffu, v, 16);
    v += __shfl_xor_sync(0xffffffffu, v, 8);
    v += __shfl_xor_sync(0xffffffffu, v, 4);
    v += __shfl_xor_sync(0xffffffffu, v, 2);
    v += __shfl_xor_sync(0xffffffffu, v, 1);
    return v;
}

// ---------------------------------------------------------------------------
// Pass A: chunk-local scan from zero state. Grid (32, NC, 4) = 1024 CTAs,
// 8 warps (warp per d, lane owns 8 n-cells). Writes RAW y_local, chunk-end
// state, sum(delta).
// ---------------------------------------------------------------------------
__global__ void __launch_bounds__(256) scan_passA(const float* __restrict__ A)
{
    const int c    = blockIdx.y;
    const int b    = blockIdx.z;
    const int wid  = threadIdx.x >> 5;
    const int lane = threadIdx.x & 31;
    const int d    = blockIdx.x * 8 + wid;
    const int no   = lane << 3;
    const float LOG2E = 1.4426950408889634f;

    float a[8];
    load8(a, A + d * 256 + no);
    #pragma unroll
    for (int j = 0; j < 8; j++) a[j] *= LOG2E;

    float s[8] = {};
    float dsum = 0.f;

    const int row0 = b * 512 + c * CT;
    const float* __restrict__ xbp = g_Bv    + (size_t)row0 * 256 + no;
    const float* __restrict__ cvp = g_Cv    + (size_t)row0 * 256 + no;
    const float* __restrict__ dvp = g_delta + (size_t)row0 * 256 + d;

    float xb[2][8], cv[2][8], dvr[2];
    load8(xb[0], xbp); load8(cv[0], cvp); dvr[0] = dvp[0];

    #pragma unroll 2
    for (int t = 0; t < CT; t++) {
        const int tp = (t + 1 < CT) ? (t + 1) : t;
        const int sp = (t + 1) & 1;
        load8(xb[sp], xbp + (size_t)tp * 256);
        load8(cv[sp], cvp + (size_t)tp * 256);
        dvr[sp] = dvp[(size_t)tp * 256];

        const int sc = t & 1;
        const float dv = dvr[sc];
        dsum += dv;
        float acc = 0.f;
        #pragma unroll
        for (int j = 0; j < 8; j++) {
            float e = ex2f(dv * a[j]);
            s[j] = fmaf(e, s[j], dv * xb[sc][j]);
            acc = fmaf(s[j], cv[sc][j], acc);
        }
        acc = warp_sum(acc);
        if (lane == 0) g_y[(size_t)(row0 + t) * 256 + d] = acc;
    }

    store8(g_state + ((size_t)(c * 4 + b) * 256 + d) * 256 + no, s);
    if (lane == 0) g_dsum[(c * 4 + b) * 256 + d] = dsum;
}

// ---------------------------------------------------------------------------
// Pass B: PARALLEL chunk combine. One thread per (b,d,n4) float4 cell:
// 65536 threads = 256 CTAs. All 8 chunk loads issued upfront (MLP=8),
// 8-step combine in registers, 8 independent stores.
// Rewrites g_state[c] from chunk-end local state to incoming state s_in.
// ---------------------------------------------------------------------------
__global__ void __launch_bounds__(256) scan_passB(const float* __restrict__ A)
{
    const int tid = blockIdx.x * 256 + threadIdx.x;   // 0..65535
    const int n4  = (tid & 63) << 2;                  // n offset (float4)
    const int d   = (tid >> 6) & 255;
    const int b   = tid >> 14;
    const float LOG2E = 1.4426950408889634f;

    float4 a4 = *(const float4*)(A + d * 256 + n4);
    a4.x *= LOG2E; a4.y *= LOG2E; a4.z *= LOG2E; a4.w *= LOG2E;

    float4 endv[NC];
    float  dsv[NC];
    #pragma unroll
    for (int c = 0; c < NC; c++) {
        endv[c] = *(const float4*)(g_state + ((size_t)(c * 4 + b) * 256 + d) * 256 + n4);
        dsv[c]  = g_dsum[(c * 4 + b) * 256 + d];
    }

    float4 sin = make_float4(0.f, 0.f, 0.f, 0.f);
    #pragma unroll
    for (int c = 0; c < NC; c++) {
        *(float4*)(g_state + ((size_t)(c * 4 + b) * 256 + d) * 256 + n4) = sin;
        const float ds = dsv[c];
        sin.x = fmaf(ex2f(ds * a4.x), sin.x, endv[c].x);
        sin.y = fmaf(ex2f(ds * a4.y), sin.y, endv[c].y);
        sin.z = fmaf(ex2f(ds * a4.z), sin.z, endv[c].z);
        sin.w = fmaf(ex2f(ds * a4.w), sin.w, endv[c].w);
    }
}

// ---------------------------------------------------------------------------
// Pass C: correction + SiLU gate. Grid (32, NC, 4) = 1024 CTAs.
// w starts at s_in; per step w *= exp(a*delta); y += C . w; gate and store.
// ---------------------------------------------------------------------------
__global__ void __launch_bounds__(256) scan_passC(const float* __restrict__ A)
{
    const int c    = blockIdx.y;
    const int b    = blockIdx.z;
    const int wid  = threadIdx.x >> 5;
    const int lane = threadIdx.x & 31;
    const int d    = blockIdx.x * 8 + wid;
    const int no   = lane << 3;
    const float LOG2E = 1.4426950408889634f;

    float a[8];
    load8(a, A + d * 256 + no);
    #pragma unroll
    for (int j = 0; j < 8; j++) a[j] *= LOG2E;

    float w[8];
    load8(w, g_state + ((size_t)(c * 4 + b) * 256 + d) * 256 + no);

    const int row0 = b * 512 + c * CT;
    const float* __restrict__ cvp = g_Cv    + (size_t)row0 * 256 + no;
    const float* __restrict__ dvp = g_delta + (size_t)row0 * 256 + d;
    const float* __restrict__ zvp = g_xproj + (size_t)row0 * 512 + 256 + d;
    float*       __restrict__ yp  = g_y     + (size_t)row0 * 256 + d;

    float cv[2][8], dvr[2], zvr[2], yvr[2];
    load8(cv[0], cvp); dvr[0] = dvp[0]; zvr[0] = zvp[0]; yvr[0] = yp[0];

    #pragma unroll 2
    for (int t = 0; t < CT; t++) {
        const int tp = (t + 1 < CT) ? (t + 1) : t;
        const int sp = (t + 1) & 1;
        load8(cv[sp], cvp + (size_t)tp * 256);
        dvr[sp] = dvp[(size_t)tp * 256];
        zvr[sp] = zvp[(size_t)tp * 512];
        yvr[sp] = yp[(size_t)tp * 256];

        const int sc = t & 1;
        const float dv = dvr[sc];
        float acc = 0.f;
        #pragma unroll
        for (int j = 0; j < 8; j++) {
            w[j] *= ex2f(dv * a[j]);
            acc = fmaf(w[j], cv[sc][j], acc);
        }
        acc = warp_sum(acc);
        if (lane == 0) {
            const float zv = zvr[sc];
            const float sg = 1.f / (1.f + __expf(-zv));
            yp[(size_t)t * 256] = (yvr[sc] + acc) * (zv * sg);
        }
    }
}

extern "C" void kernel_launch(void* const* d_in, const int* in_sizes, int n_in,
                              void* d_out, int out_size)
{
    const float* x       = (const float*)d_in[0];
    const float* W_in    = (const float*)d_in[1];
    const float* W_delta = (const float*)d_in[2];
    const float* W_B     = (const float*)d_in[3];
    const float* W_C     = (const float*)d_in[4];
    const float* W_out   = (const float*)d_in[5];
    const float* A       = (const float*)d_in[6];
    float* out = (float*)d_out;

    k_in_proj <<<dim3(8, 32),     128>>>(x, W_in);
    k_dbc     <<<dim3(4, 32, 3),  128>>>(W_delta, W_B, W_C);
    scan_passA<<<dim3(32, NC, 4), 256>>>(A);
    scan_passB<<<256,             256>>>(A);
    scan_passC<<<dim3(32, NC, 4), 256>>>(A);
    k_out_proj<<<dim3(2, 64),     128>>>(W_out, out);
}

// round 8
// speedup vs baseline: 1.6632x; 1.1778x over previous
#include <cuda_runtime.h>
#include <cuda_bf16.h>
#include <cstdint>

// ---------------------------------------------------------------------------
// MambaBlock: B=4, L=512, d_model=128, d_inner=d_state=256, rows = 2048
//   xproj = x @ W_in ; delta/Bv/Cv = xs @ {Wd,Wb,Wc} (fused, xb=Bv*xs epilogue)
//   chunked scan (NC=8 x CT=64): passA local scan (writes raw y, chunk states,
//   dsum), passC: per-CTA prefix combine (replaces passB) + correction + gate.
//   out = g @ W_out
// kernel_launch performs kernel launches ONLY (graph-capture safe).
// ---------------------------------------------------------------------------

#define ROWS 2048
#define DI   256
#define DM   128
#define NC   8
#define CT   64

__device__ float g_xproj[ROWS * 512];
__device__ float g_delta[ROWS * DI];
__device__ float g_Bv[ROWS * DI];     // xb = Bv * xs after k_dbc
__device__ float g_Cv[ROWS * DI];
__device__ float g_y[ROWS * DI];
__device__ float g_state[NC * 4 * DI * DI];   // [c][b][d][n]
__device__ float g_dsum[NC * 4 * DI];         // [c][b][d]

__device__ __forceinline__ float ex2f(float x) {
    float r;
    asm("ex2.approx.ftz.f32 %0, %1;" : "=f"(r) : "f"(x));
    return r;
}

__device__ __forceinline__ void load8(float* r, const float* __restrict__ p) {
    float4 u = *(const float4*)p;
    float4 v = *(const float4*)(p + 4);
    r[0] = u.x; r[1] = u.y; r[2] = u.z; r[3] = u.w;
    r[4] = v.x; r[5] = v.y; r[6] = v.z; r[7] = v.w;
}
__device__ __forceinline__ void store8(float* __restrict__ p, const float* r) {
    *(float4*)p       = make_float4(r[0], r[1], r[2], r[3]);
    *(float4*)(p + 4) = make_float4(r[4], r[5], r[6], r[7]);
}

// ---------------------------------------------------------------------------
// fp32 tiled GEMM body, double-buffered smem: 64x64 tile, BK=16, 256 thr,
// 4x4 accumulators (R6-measured configuration).
// ---------------------------------------------------------------------------
__device__ __forceinline__ void gemm_body(
    const float* __restrict__ A, const float* __restrict__ B, float* __restrict__ C,
    int K, int lda, int ldb, int ldc, bool mul_xs)
{
    __shared__ float As[2][16][64];
    __shared__ float Bs[2][16][64];

    const int tx = threadIdx.x & 15;
    const int ty = threadIdx.x >> 4;
    const int rowBase = blockIdx.y * 64;
    const int colBase = blockIdx.x * 64;

    const int lr = threadIdx.x >> 2;
    const int lk = (threadIdx.x & 3) << 2;
    const int bk = threadIdx.x >> 4;
    const int bc = (threadIdx.x & 15) << 2;

    const float* Aptr = A + (size_t)(rowBase + lr) * lda + lk;
    const float* Bptr = B + (size_t)bk * ldb + colBase + bc;

    float acc[4][4] = {};
    const int nT = K >> 4;

    float4 av = *(const float4*)Aptr;
    float4 bv = *(const float4*)Bptr;

    for (int kt = 0; kt < nT; kt++) {
        const int p = kt & 1;
        As[p][lk + 0][lr] = av.x;
        As[p][lk + 1][lr] = av.y;
        As[p][lk + 2][lr] = av.z;
        As[p][lk + 3][lr] = av.w;
        *(float4*)&Bs[p][bk][bc] = bv;
        __syncthreads();

        if (kt + 1 < nT) {
            av = *(const float4*)(Aptr + (kt + 1) * 16);
            bv = *(const float4*)(Bptr + (size_t)(kt + 1) * 16 * ldb);
        }

        #pragma unroll
        for (int k = 0; k < 16; k++) {
            float4 a4 = *(const float4*)&As[p][k][ty << 2];
            float4 b4 = *(const float4*)&Bs[p][k][tx << 2];
            acc[0][0] += a4.x * b4.x; acc[0][1] += a4.x * b4.y;
            acc[0][2] += a4.x * b4.z; acc[0][3] += a4.x * b4.w;
            acc[1][0] += a4.y * b4.x; acc[1][1] += a4.y * b4.y;
            acc[1][2] += a4.y * b4.z; acc[1][3] += a4.y * b4.w;
            acc[2][0] += a4.z * b4.x; acc[2][1] += a4.z * b4.y;
            acc[2][2] += a4.z * b4.z; acc[2][3] += a4.z * b4.w;
            acc[3][0] += a4.w * b4.x; acc[3][1] += a4.w * b4.y;
            acc[3][2] += a4.w * b4.z; acc[3][3] += a4.w * b4.w;
        }
        __syncthreads();
    }

    #pragma unroll
    for (int i = 0; i < 4; i++) {
        const int row = rowBase + (ty << 2) + i;
        float4 v = make_float4(acc[i][0], acc[i][1], acc[i][2], acc[i][3]);
        if (mul_xs) {
            float4 xs4 = *(const float4*)(g_xproj + (size_t)row * 512 + colBase + (tx << 2));
            v.x *= xs4.x; v.y *= xs4.y; v.z *= xs4.z; v.w *= xs4.w;
        }
        *(float4*)(C + (size_t)row * ldc + colBase + (tx << 2)) = v;
    }
}

__global__ void __launch_bounds__(256) k_in_proj(const float* __restrict__ x,
                                                 const float* __restrict__ W_in) {
    gemm_body(x, W_in, g_xproj, DM, DM, 512, 512, false);
}

__global__ void __launch_bounds__(256) k_dbc(const float* __restrict__ Wd,
                                             const float* __restrict__ Wb,
                                             const float* __restrict__ Wc) {
    const float* W = (blockIdx.z == 0) ? Wd : ((blockIdx.z == 1) ? Wb : Wc);
    float* C = (blockIdx.z == 0) ? g_delta : ((blockIdx.z == 1) ? g_Bv : g_Cv);
    gemm_body(g_xproj, W, C, DI, 512, DI, DI, blockIdx.z == 1);
}

__global__ void __launch_bounds__(256) k_out_proj(const float* __restrict__ W_out,
                                                  float* __restrict__ out) {
    __shared__ float As[2][16][32];
    __shared__ float Bs[2][16][64];

    const int tx = threadIdx.x & 15;
    const int ty = threadIdx.x >> 4;
    const int rowBase = blockIdx.y * 32;
    const int colBase = blockIdx.x * 64;

    const int lr = threadIdx.x >> 3;
    const int lk = (threadIdx.x & 7) << 1;
    const int bk = threadIdx.x >> 4;
    const int bc = (threadIdx.x & 15) << 2;

    const float* Aptr = g_y + (size_t)(rowBase + lr) * DI + lk;
    const float* Bptr = W_out + (size_t)bk * DM + colBase + bc;

    float acc[2][4] = {};
    const int nT = DI >> 4;

    float2 av = *(const float2*)Aptr;
    float4 bv = *(const float4*)Bptr;

    for (int kt = 0; kt < nT; kt++) {
        const int p = kt & 1;
        As[p][lk + 0][lr] = av.x;
        As[p][lk + 1][lr] = av.y;
        *(float4*)&Bs[p][bk][bc] = bv;
        __syncthreads();

        if (kt + 1 < nT) {
            av = *(const float2*)(Aptr + (kt + 1) * 16);
            bv = *(const float4*)(Bptr + (size_t)(kt + 1) * 16 * DM);
        }

        #pragma unroll
        for (int k = 0; k < 16; k++) {
            float a0 = As[p][k][(ty << 1) + 0];
            float a1 = As[p][k][(ty << 1) + 1];
            float4 b4 = *(const float4*)&Bs[p][k][tx << 2];
            acc[0][0] += a0 * b4.x; acc[0][1] += a0 * b4.y;
            acc[0][2] += a0 * b4.z; acc[0][3] += a0 * b4.w;
            acc[1][0] += a1 * b4.x; acc[1][1] += a1 * b4.y;
            acc[1][2] += a1 * b4.z; acc[1][3] += a1 * b4.w;
        }
        __syncthreads();
    }

    #pragma unroll
    for (int i = 0; i < 2; i++) {
        float4 v = make_float4(acc[i][0], acc[i][1], acc[i][2], acc[i][3]);
        *(float4*)(out + (size_t)(rowBase + (ty << 1) + i) * DM + colBase + (tx << 2)) = v;
    }
}

// ---------------------------------------------------------------------------
// Transpose-style reduction of 8 per-lane partials p[0..7] (each the lane's
// partial for one step). After: every lane holds the FULL 32-lane sum for
// step (lane & 7). Cost: 9 SHFL vs 40 for eight 5-level butterflies.
// ---------------------------------------------------------------------------
__device__ __forceinline__ void treduce8(float* p, int lane) {
    #pragma unroll
    for (int k = 0; k < 8; k += 2) {                 // level 1 (step bit0 <- lane bit0)
        float mine  = (lane & 1) ? p[k] : p[k + 1];
        float other = __shfl_xor_sync(0xffffffffu, mine, 1);
        float keep  = (lane & 1) ? p[k + 1] : p[k];
        p[k >> 1] = keep + other;
    }
    #pragma unroll
    for (int k = 0; k < 4; k += 2) {                 // level 2
        float mine  = (lane & 2) ? p[k] : p[k + 1];
        float other = __shfl_xor_sync(0xffffffffu, mine, 2);
        float keep  = (lane & 2) ? p[k + 1] : p[k];
        p[k >> 1] = keep + other;
    }
    {                                                // level 3
        float mine  = (lane & 4) ? p[0] : p[1];
        float other = __shfl_xor_sync(0xffffffffu, mine, 4);
        float keep  = (lane & 4) ? p[1] : p[0];
        p[0] = keep + other;
    }
    p[0] += __shfl_xor_sync(0xffffffffu, p[0], 8);
    p[0] += __shfl_xor_sync(0xffffffffu, p[0], 16);
}

// ---------------------------------------------------------------------------
// Pass A: chunk-local scan from zero state. Grid (32, NC, 4) = 1024 CTAs,
// 8 warps (warp per d, lane owns 8 n-cells). Writes RAW y, chunk-end state,
// sum(delta). Steps processed in groups of 8 with batched reduction.
// ---------------------------------------------------------------------------
__global__ void __launch_bounds__(256) scan_passA(const float* __restrict__ A)
{
    const int c    = blockIdx.y;
    const int b    = blockIdx.z;
    const int wid  = threadIdx.x >> 5;
    const int lane = threadIdx.x & 31;
    const int d    = blockIdx.x * 8 + wid;
    const int no   = lane << 3;
    const float LOG2E = 1.4426950408889634f;

    float a[8];
    load8(a, A + d * 256 + no);
    #pragma unroll
    for (int j = 0; j < 8; j++) a[j] *= LOG2E;

    float s[8] = {};
    float dsum = 0.f;

    const int row0 = b * 512 + c * CT;
    const float* __restrict__ xbp = g_Bv    + (size_t)row0 * 256 + no;
    const float* __restrict__ cvp = g_Cv    + (size_t)row0 * 256 + no;
    const float* __restrict__ dvp = g_delta + (size_t)row0 * 256 + d;

    float xb[2][8], cv[2][8], dvr[2];
    load8(xb[0], xbp); load8(cv[0], cvp); dvr[0] = dvp[0];

    float p[8];

    for (int g = 0; g < CT / 8; g++) {
        #pragma unroll
        for (int t8 = 0; t8 < 8; t8++) {
            const int t  = g * 8 + t8;
            const int tp = (t + 1 < CT) ? (t + 1) : t;
            const int sp = (t + 1) & 1;
            load8(xb[sp], xbp + (size_t)tp * 256);
            load8(cv[sp], cvp + (size_t)tp * 256);
            dvr[sp] = dvp[(size_t)tp * 256];

            const int sc = t & 1;
            const float dv = dvr[sc];
            dsum += dv;
            float acc = 0.f;
            #pragma unroll
            for (int j = 0; j < 8; j++) {
                float e = ex2f(dv * a[j]);
                s[j] = fmaf(e, s[j], dv * xb[sc][j]);
                acc = fmaf(s[j], cv[sc][j], acc);
            }
            p[t8] = acc;
        }
        treduce8(p, lane);
        if (lane < 8)
            g_y[(size_t)(row0 + g * 8 + lane) * 256 + d] = p[0];
    }

    store8(g_state + ((size_t)(c * 4 + b) * 256 + d) * 256 + no, s);
    if (lane == 0) g_dsum[(c * 4 + b) * 256 + d] = dsum;
}

// ---------------------------------------------------------------------------
// Pass C: prefix combine (inlined, replaces passB) + correction + SiLU gate.
// Grid (32, NC, 4). s_in built from chunk-end states 0..c-1 in registers;
// then w *= exp(a*delta) per step, y += C.w, gate, store.
// ---------------------------------------------------------------------------
__global__ void __launch_bounds__(256) scan_passC(const float* __restrict__ A)
{
    const int c    = blockIdx.y;
    const int b    = blockIdx.z;
    const int wid  = threadIdx.x >> 5;
    const int lane = threadIdx.x & 31;
    const int d    = blockIdx.x * 8 + wid;
    const int no   = lane << 3;
    const float LOG2E = 1.4426950408889634f;

    float a[8];
    load8(a, A + d * 256 + no);
    #pragma unroll
    for (int j = 0; j < 8; j++) a[j] *= LOG2E;

    // inline chunk-prefix combine: s_in = sum over c'<c with chunk decays
    float w[8] = {};
    for (int cp = 0; cp < c; cp++) {
        float endv[8];
        load8(endv, g_state + ((size_t)(cp * 4 + b) * 256 + d) * 256 + no);
        const float ds = g_dsum[(cp * 4 + b) * 256 + d];
        #pragma unroll
        for (int j = 0; j < 8; j++)
            w[j] = fmaf(ex2f(ds * a[j]), w[j], endv[j]);
    }

    const int row0 = b * 512 + c * CT;
    const float* __restrict__ cvp = g_Cv    + (size_t)row0 * 256 + no;
    const float* __restrict__ dvp = g_delta + (size_t)row0 * 256 + d;
    const float* __restrict__ zvp = g_xproj + (size_t)row0 * 512 + 256 + d;
    float*       __restrict__ yp  = g_y     + (size_t)row0 * 256 + d;

    float cv[2][8], dvr[2];
    load8(cv[0], cvp); dvr[0] = dvp[0];

    float p[8];

    for (int g = 0; g < CT / 8; g++) {
        // prefetch this group's gate operands (used ~8 steps later)
        const int tg = g * 8 + (lane & 7);
        const float zq = zvp[(size_t)tg * 512];
        const float yq = yp[(size_t)tg * 256];

        #pragma unroll
        for (int t8 = 0; t8 < 8; t8++) {
            const int t  = g * 8 + t8;
            const int tp = (t + 1 < CT) ? (t + 1) : t;
            const int sp = (t + 1) & 1;
            load8(cv[sp], cvp + (size_t)tp * 256);
            dvr[sp] = dvp[(size_t)tp * 256];

            const int sc = t & 1;
            const float dv = dvr[sc];
            float acc = 0.f;
            #pragma unroll
            for (int j = 0; j < 8; j++) {
                w[j] *= ex2f(dv * a[j]);
                acc = fmaf(w[j], cv[sc][j], acc);
            }
            p[t8] = acc;
        }
        treduce8(p, lane);
        if (lane < 8) {
            const float sg = 1.f / (1.f + __expf(-zq));
            yp[(size_t)(g * 8 + lane) * 256] = (yq + p[0]) * (zq * sg);
        }
    }
}

extern "C" void kernel_launch(void* const* d_in, const int* in_sizes, int n_in,
                              void* d_out, int out_size)
{
    const float* x       = (const float*)d_in[0];
    const float* W_in    = (const float*)d_in[1];
    const float* W_delta = (const float*)d_in[2];
    const float* W_B     = (const float*)d_in[3];
    const float* W_C     = (const float*)d_in[4];
    const float* W_out   = (const float*)d_in[5];
    const float* A       = (const float*)d_in[6];
    float* out = (float*)d_out;

    k_in_proj <<<dim3(8, 32),     256>>>(x, W_in);
    k_dbc     <<<dim3(4, 32, 3),  256>>>(W_delta, W_B, W_C);
    scan_passA<<<dim3(32, NC, 4), 256>>>(A);
    scan_passC<<<dim3(32, NC, 4), 256>>>(A);
    k_out_proj<<<dim3(2, 64),     256>>>(W_out, out);
}

// round 9
// speedup vs baseline: 1.7927x; 1.0779x over previous
#include <cuda_runtime.h>
#include <cuda_bf16.h>
#include <cstdint>

// ---------------------------------------------------------------------------
// MambaBlock: B=4, L=512, d_model=128, d_inner=d_state=256, rows = 2048
//   xproj = x @ W_in ; delta/Bv/Cv = xs @ {Wd,Wb,Wc} (fused, xb=Bv*xs epilogue)
//   chunked scan (NC=8 x CT=64): passA local scan (warp owns TWO d-channels:
//   cv/xb loaded once per warp serve both), passC prefix-combine + correction
//   + silu gate ; out = g @ W_out
// kernel_launch performs kernel launches ONLY (graph-capture safe).
// ---------------------------------------------------------------------------

#define ROWS 2048
#define DI   256
#define DM   128
#define NC   8
#define CT   64

__device__ float g_xproj[ROWS * 512];
__device__ float g_delta[ROWS * DI];
__device__ float g_Bv[ROWS * DI];     // xb = Bv * xs after k_dbc
__device__ float g_Cv[ROWS * DI];
__device__ float g_y[ROWS * DI];
__device__ float g_state[NC * 4 * DI * DI];   // [c][b][d][n]
__device__ float g_dsum[NC * 4 * DI];         // [c][b][d]

__device__ __forceinline__ float ex2f(float x) {
    float r;
    asm("ex2.approx.ftz.f32 %0, %1;" : "=f"(r) : "f"(x));
    return r;
}

__device__ __forceinline__ void load8(float* r, const float* __restrict__ p) {
    float4 u = *(const float4*)p;
    float4 v = *(const float4*)(p + 4);
    r[0] = u.x; r[1] = u.y; r[2] = u.z; r[3] = u.w;
    r[4] = v.x; r[5] = v.y; r[6] = v.z; r[7] = v.w;
}
__device__ __forceinline__ void store8(float* __restrict__ p, const float* r) {
    *(float4*)p       = make_float4(r[0], r[1], r[2], r[3]);
    *(float4*)(p + 4) = make_float4(r[4], r[5], r[6], r[7]);
}

// ---------------------------------------------------------------------------
// fp32 tiled GEMM body, double-buffered smem: 64x64 tile, BK=16, 256 thr,
// 4x4 accumulators (R6-measured configuration).
// ---------------------------------------------------------------------------
__device__ __forceinline__ void gemm_body(
    const float* __restrict__ A, const float* __restrict__ B, float* __restrict__ C,
    int K, int lda, int ldb, int ldc, bool mul_xs)
{
    __shared__ float As[2][16][64];
    __shared__ float Bs[2][16][64];

    const int tx = threadIdx.x & 15;
    const int ty = threadIdx.x >> 4;
    const int rowBase = blockIdx.y * 64;
    const int colBase = blockIdx.x * 64;

    const int lr = threadIdx.x >> 2;
    const int lk = (threadIdx.x & 3) << 2;
    const int bk = threadIdx.x >> 4;
    const int bc = (threadIdx.x & 15) << 2;

    const float* Aptr = A + (size_t)(rowBase + lr) * lda + lk;
    const float* Bptr = B + (size_t)bk * ldb + colBase + bc;

    float acc[4][4] = {};
    const int nT = K >> 4;

    float4 av = *(const float4*)Aptr;
    float4 bv = *(const float4*)Bptr;

    for (int kt = 0; kt < nT; kt++) {
        const int p = kt & 1;
        As[p][lk + 0][lr] = av.x;
        As[p][lk + 1][lr] = av.y;
        As[p][lk + 2][lr] = av.z;
        As[p][lk + 3][lr] = av.w;
        *(float4*)&Bs[p][bk][bc] = bv;
        __syncthreads();

        if (kt + 1 < nT) {
            av = *(const float4*)(Aptr + (kt + 1) * 16);
            bv = *(const float4*)(Bptr + (size_t)(kt + 1) * 16 * ldb);
        }

        #pragma unroll
        for (int k = 0; k < 16; k++) {
            float4 a4 = *(const float4*)&As[p][k][ty << 2];
            float4 b4 = *(const float4*)&Bs[p][k][tx << 2];
            acc[0][0] += a4.x * b4.x; acc[0][1] += a4.x * b4.y;
            acc[0][2] += a4.x * b4.z; acc[0][3] += a4.x * b4.w;
            acc[1][0] += a4.y * b4.x; acc[1][1] += a4.y * b4.y;
            acc[1][2] += a4.y * b4.z; acc[1][3] += a4.y * b4.w;
            acc[2][0] += a4.z * b4.x; acc[2][1] += a4.z * b4.y;
            acc[2][2] += a4.z * b4.z; acc[2][3] += a4.z * b4.w;
            acc[3][0] += a4.w * b4.x; acc[3][1] += a4.w * b4.y;
            acc[3][2] += a4.w * b4.z; acc[3][3] += a4.w * b4.w;
        }
        __syncthreads();
    }

    #pragma unroll
    for (int i = 0; i < 4; i++) {
        const int row = rowBase + (ty << 2) + i;
        float4 v = make_float4(acc[i][0], acc[i][1], acc[i][2], acc[i][3]);
        if (mul_xs) {
            float4 xs4 = *(const float4*)(g_xproj + (size_t)row * 512 + colBase + (tx << 2));
            v.x *= xs4.x; v.y *= xs4.y; v.z *= xs4.z; v.w *= xs4.w;
        }
        *(float4*)(C + (size_t)row * ldc + colBase + (tx << 2)) = v;
    }
}

__global__ void __launch_bounds__(256) k_in_proj(const float* __restrict__ x,
                                                 const float* __restrict__ W_in) {
    gemm_body(x, W_in, g_xproj, DM, DM, 512, 512, false);
}

__global__ void __launch_bounds__(256) k_dbc(const float* __restrict__ Wd,
                                             const float* __restrict__ Wb,
                                             const float* __restrict__ Wc) {
    const float* W = (blockIdx.z == 0) ? Wd : ((blockIdx.z == 1) ? Wb : Wc);
    float* C = (blockIdx.z == 0) ? g_delta : ((blockIdx.z == 1) ? g_Bv : g_Cv);
    gemm_body(g_xproj, W, C, DI, 512, DI, DI, blockIdx.z == 1);
}

__global__ void __launch_bounds__(256) k_out_proj(const float* __restrict__ W_out,
                                                  float* __restrict__ out) {
    __shared__ float As[2][16][32];
    __shared__ float Bs[2][16][64];

    const int tx = threadIdx.x & 15;
    const int ty = threadIdx.x >> 4;
    const int rowBase = blockIdx.y * 32;
    const int colBase = blockIdx.x * 64;

    const int lr = threadIdx.x >> 3;
    const int lk = (threadIdx.x & 7) << 1;
    const int bk = threadIdx.x >> 4;
    const int bc = (threadIdx.x & 15) << 2;

    const float* Aptr = g_y + (size_t)(rowBase + lr) * DI + lk;
    const float* Bptr = W_out + (size_t)bk * DM + colBase + bc;

    float acc[2][4] = {};
    const int nT = DI >> 4;

    float2 av = *(const float2*)Aptr;
    float4 bv = *(const float4*)Bptr;

    for (int kt = 0; kt < nT; kt++) {
        const int p = kt & 1;
        As[p][lk + 0][lr] = av.x;
        As[p][lk + 1][lr] = av.y;
        *(float4*)&Bs[p][bk][bc] = bv;
        __syncthreads();

        if (kt + 1 < nT) {
            av = *(const float2*)(Aptr + (kt + 1) * 16);
            bv = *(const float4*)(Bptr + (size_t)(kt + 1) * 16 * DM);
        }

        #pragma unroll
        for (int k = 0; k < 16; k++) {
            float a0 = As[p][k][(ty << 1) + 0];
            float a1 = As[p][k][(ty << 1) + 1];
            float4 b4 = *(const float4*)&Bs[p][k][tx << 2];
            acc[0][0] += a0 * b4.x; acc[0][1] += a0 * b4.y;
            acc[0][2] += a0 * b4.z; acc[0][3] += a0 * b4.w;
            acc[1][0] += a1 * b4.x; acc[1][1] += a1 * b4.y;
            acc[1][2] += a1 * b4.z; acc[1][3] += a1 * b4.w;
        }
        __syncthreads();
    }

    #pragma unroll
    for (int i = 0; i < 2; i++) {
        float4 v = make_float4(acc[i][0], acc[i][1], acc[i][2], acc[i][3]);
        *(float4*)(out + (size_t)(rowBase + (ty << 1) + i) * DM + colBase + (tx << 2)) = v;
    }
}

// ---------------------------------------------------------------------------
// Transpose-style reduction of 8 per-lane partials p[0..7]. After: every lane
// holds the FULL 32-lane sum for step (lane & 7). 9 SHFL total.
// ---------------------------------------------------------------------------
__device__ __forceinline__ void treduce8(float* p, int lane) {
    #pragma unroll
    for (int k = 0; k < 8; k += 2) {
        float mine  = (lane & 1) ? p[k] : p[k + 1];
        float other = __shfl_xor_sync(0xffffffffu, mine, 1);
        float keep  = (lane & 1) ? p[k + 1] : p[k];
        p[k >> 1] = keep + other;
    }
    #pragma unroll
    for (int k = 0; k < 4; k += 2) {
        float mine  = (lane & 2) ? p[k] : p[k + 1];
        float other = __shfl_xor_sync(0xffffffffu, mine, 2);
        float keep  = (lane & 2) ? p[k + 1] : p[k];
        p[k >> 1] = keep + other;
    }
    {
        float mine  = (lane & 4) ? p[0] : p[1];
        float other = __shfl_xor_sync(0xffffffffu, mine, 4);
        float keep  = (lane & 4) ? p[1] : p[0];
        p[0] = keep + other;
    }
    p[0] += __shfl_xor_sync(0xffffffffu, p[0], 8);
    p[0] += __shfl_xor_sync(0xffffffffu, p[0], 16);
}

// ---------------------------------------------------------------------------
// Pass A (m=2): chunk-local scan. Grid (32, NC, 4), 128 threads (4 warps).
// Each warp owns TWO d-channels; lane holds 8 n-cells for each. cv/xb loads
// are shared by both d's (halves L1 traffic per cell).
// ---------------------------------------------------------------------------
__global__ void __launch_bounds__(128) scan_passA(const float* __restrict__ A)
{
    const int c    = blockIdx.y;
    const int b    = blockIdx.z;
    const int wid  = threadIdx.x >> 5;
    const int lane = threadIdx.x & 31;
    const int d0   = blockIdx.x * 8 + wid * 2;     // owns d0, d0+1
    const int no   = lane << 3;
    const float LOG2E = 1.4426950408889634f;

    float a0[8], a1[8];
    load8(a0, A + (size_t)d0 * 256 + no);
    load8(a1, A + (size_t)(d0 + 1) * 256 + no);
    #pragma unroll
    for (int j = 0; j < 8; j++) { a0[j] *= LOG2E; a1[j] *= LOG2E; }

    float s0[8] = {}, s1[8] = {};
    float ds0 = 0.f, ds1 = 0.f;

    const int row0 = b * 512 + c * CT;
    const float* __restrict__ xbp = g_Bv    + (size_t)row0 * 256 + no;
    const float* __restrict__ cvp = g_Cv    + (size_t)row0 * 256 + no;
    const float* __restrict__ dvp = g_delta + (size_t)row0 * 256;

    float xb[2][8], cv[2][8], dv0r[2], dv1r[2];
    load8(xb[0], xbp); load8(cv[0], cvp);
    dv0r[0] = dvp[d0]; dv1r[0] = dvp[d0 + 1];

    float p0[8], p1[8];

    for (int g = 0; g < CT / 8; g++) {
        #pragma unroll
        for (int t8 = 0; t8 < 8; t8++) {
            const int t  = g * 8 + t8;
            const int tp = (t + 1 < CT) ? (t + 1) : t;
            const int sp = (t + 1) & 1;
            load8(xb[sp], xbp + (size_t)tp * 256);
            load8(cv[sp], cvp + (size_t)tp * 256);
            dv0r[sp] = dvp[(size_t)tp * 256 + d0];
            dv1r[sp] = dvp[(size_t)tp * 256 + d0 + 1];

            const int sc = t & 1;
            const float dv0 = dv0r[sc];
            const float dv1 = dv1r[sc];
            ds0 += dv0; ds1 += dv1;
            float acc0 = 0.f, acc1 = 0.f;
            #pragma unroll
            for (int j = 0; j < 8; j++) {
                const float bx = xb[sc][j];
                const float cj = cv[sc][j];
                s0[j] = fmaf(ex2f(dv0 * a0[j]), s0[j], dv0 * bx);
                acc0  = fmaf(s0[j], cj, acc0);
                s1[j] = fmaf(ex2f(dv1 * a1[j]), s1[j], dv1 * bx);
                acc1  = fmaf(s1[j], cj, acc1);
            }
            p0[t8] = acc0; p1[t8] = acc1;
        }
        treduce8(p0, lane);
        treduce8(p1, lane);
        if (lane < 8) {
            g_y[(size_t)(row0 + g * 8 + lane) * 256 + d0]     = p0[0];
            g_y[(size_t)(row0 + g * 8 + lane) * 256 + d0 + 1] = p1[0];
        }
    }

    store8(g_state + ((size_t)(c * 4 + b) * 256 + d0)     * 256 + no, s0);
    store8(g_state + ((size_t)(c * 4 + b) * 256 + d0 + 1) * 256 + no, s1);
    if (lane == 0) {
        g_dsum[(c * 4 + b) * 256 + d0]     = ds0;
        g_dsum[(c * 4 + b) * 256 + d0 + 1] = ds1;
    }
}

// ---------------------------------------------------------------------------
// Pass C (m=2): prefix combine + correction + SiLU gate. Grid (32, NC, 4),
// 128 threads. Warp owns two d-channels, cv shared.
// ---------------------------------------------------------------------------
__global__ void __launch_bounds__(128) scan_passC(const float* __restrict__ A)
{
    const int c    = blockIdx.y;
    const int b    = blockIdx.z;
    const int wid  = threadIdx.x >> 5;
    const int lane = threadIdx.x & 31;
    const int d0   = blockIdx.x * 8 + wid * 2;
    const int no   = lane << 3;
    const float LOG2E = 1.4426950408889634f;

    float a0[8], a1[8];
    load8(a0, A + (size_t)d0 * 256 + no);
    load8(a1, A + (size_t)(d0 + 1) * 256 + no);
    #pragma unroll
    for (int j = 0; j < 8; j++) { a0[j] *= LOG2E; a1[j] *= LOG2E; }

    // prefix combine: w = incoming state for chunk c (both d's)
    float w0[8] = {}, w1[8] = {};
    for (int cp = 0; cp < c; cp++) {
        float e0[8], e1[8];
        load8(e0, g_state + ((size_t)(cp * 4 + b) * 256 + d0)     * 256 + no);
        load8(e1, g_state + ((size_t)(cp * 4 + b) * 256 + d0 + 1) * 256 + no);
        const float dsa = g_dsum[(cp * 4 + b) * 256 + d0];
        const float dsb = g_dsum[(cp * 4 + b) * 256 + d0 + 1];
        #pragma unroll
        for (int j = 0; j < 8; j++) {
            w0[j] = fmaf(ex2f(dsa * a0[j]), w0[j], e0[j]);
            w1[j] = fmaf(ex2f(dsb * a1[j]), w1[j], e1[j]);
        }
    }

    const int row0 = b * 512 + c * CT;
    const float* __restrict__ cvp = g_Cv    + (size_t)row0 * 256 + no;
    const float* __restrict__ dvp = g_delta + (size_t)row0 * 256;
    const float* __restrict__ zvp = g_xproj + (size_t)row0 * 512 + 256;
    float*       __restrict__ yp  = g_y     + (size_t)row0 * 256;

    float cv[2][8], dv0r[2], dv1r[2];
    load8(cv[0], cvp);
    dv0r[0] = dvp[d0]; dv1r[0] = dvp[d0 + 1];

    float p0[8], p1[8];

    for (int g = 0; g < CT / 8; g++) {
        // prefetch gate operands for this group (used after the 8 steps)
        const int tg = g * 8 + (lane & 7);
        const float zq0 = zvp[(size_t)tg * 512 + d0];
        const float zq1 = zvp[(size_t)tg * 512 + d0 + 1];
        const float yq0 = yp[(size_t)tg * 256 + d0];
        const float yq1 = yp[(size_t)tg * 256 + d0 + 1];

        #pragma unroll
        for (int t8 = 0; t8 < 8; t8++) {
            const int t  = g * 8 + t8;
            const int tp = (t + 1 < CT) ? (t + 1) : t;
            const int sp = (t + 1) & 1;
            load8(cv[sp], cvp + (size_t)tp * 256);
            dv0r[sp] = dvp[(size_t)tp * 256 + d0];
            dv1r[sp] = dvp[(size_t)tp * 256 + d0 + 1];

            const int sc = t & 1;
            const float dv0 = dv0r[sc];
            const float dv1 = dv1r[sc];
            float acc0 = 0.f, acc1 = 0.f;
            #pragma unroll
            for (int j = 0; j < 8; j++) {
                const float cj = cv[sc][j];
                w0[j] *= ex2f(dv0 * a0[j]);
                acc0 = fmaf(w0[j], cj, acc0);
                w1[j] *= ex2f(dv1 * a1[j]);
                acc1 = fmaf(w1[j], cj, acc1);
            }
            p0[t8] = acc0; p1[t8] = acc1;
        }
        treduce8(p0, lane);
        treduce8(p1, lane);
        if (lane < 8) {
            const float sg0 = 1.f / (1.f + __expf(-zq0));
            const float sg1 = 1.f / (1.f + __expf(-zq1));
            yp[(size_t)(g * 8 + lane) * 256 + d0]     = (yq0 + p0[0]) * (zq0 * sg0);
            yp[(size_t)(g * 8 + lane) * 256 + d0 + 1] = (yq1 + p1[0]) * (zq1 * sg1);
        }
    }
}

extern "C" void kernel_launch(void* const* d_in, const int* in_sizes, int n_in,
                              void* d_out, int out_size)
{
    const float* x       = (const float*)d_in[0];
    const float* W_in    = (const float*)d_in[1];
    const float* W_delta = (const float*)d_in[2];
    const float* W_B     = (const float*)d_in[3];
    const float* W_C     = (const float*)d_in[4];
    const float* W_out   = (const float*)d_in[5];
    const float* A       = (const float*)d_in[6];
    float* out = (float*)d_out;

    k_in_proj <<<dim3(8, 32),     256>>>(x, W_in);
    k_dbc     <<<dim3(4, 32, 3),  256>>>(W_delta, W_B, W_C);
    scan_passA<<<dim3(32, NC, 4), 128>>>(A);
    scan_passC<<<dim3(32, NC, 4), 128>>>(A);
    k_out_proj<<<dim3(2, 64),     256>>>(W_out, out);
}